// round 1
// baseline (speedup 1.0000x reference)
#include <cuda_runtime.h>
#include <stdint.h>

#define N_NODES     50000
#define N_EDGES     500000
#define D_FEAT      128
#define OUT_CLASSES 64
#define PDIM        128   // [0:64) = Pu, [64:128) = Pv

// Scratch: per-node precomputed projections. 50000*128*4B = 25.6 MB (fits L2).
__device__ __align__(16) float g_P[N_NODES * PDIM];
__device__ int g_idx_is64;

// ---------------------------------------------------------------------------
// Probe: detect whether index arrays are int64 or int32 (JAX may downcast).
// If the buffer really holds int64 node ids, the first 8 int64 reads are all
// in [0, N_NODES). If it holds int32, an int64 read packs two indices and is
// almost surely huge.
// ---------------------------------------------------------------------------
__global__ void probe_idx_kernel(const void* __restrict__ srcp) {
    const long long* s64 = (const long long*)srcp;
    int ok = 1;
    #pragma unroll
    for (int i = 0; i < 8; ++i) {
        long long v = s64[i];
        if (v < 0 || v >= (long long)N_NODES) ok = 0;
    }
    g_idx_is64 = ok;
}

// ---------------------------------------------------------------------------
// Kernel 1: node projection GEMM.
//   P[n][j] = sum_k h[n][k] * Wt[k][j]
// where Wt[k][j] = (j<64) ? W[j][k] : W[j-64][128+k]   (W is [64][256] row-major)
//
// Tiling: 64 nodes x 128 outputs per CTA, 256 threads, each thread computes a
// 4(node) x 8(out) register tile. W (64KB) and the transposed h tile staged in
// shared memory. ~98.5 KB dynamic smem, 2 CTAs/SM.
// ---------------------------------------------------------------------------
#define TILE_NODES 64
#define WPAD 132   // 128 + 4: keeps float4 rows 16B-aligned, low STS conflicts
#define HPAD 65    // 128-wide transpose store conflict-free (stride 65 mod 32 = 1)

__global__ __launch_bounds__(256, 2)
void node_gemm_kernel(const float* __restrict__ h,
                      const float* __restrict__ W) {
    extern __shared__ float sh[];
    float* Wt = sh;                       // [128][WPAD]
    float* hs = sh + 128 * WPAD;          // [128][HPAD]

    const int tid = threadIdx.x;
    const int n0  = blockIdx.x * TILE_NODES;

    // Stage W, transformed+transposed: Wt[k][j]
    for (int idx = tid; idx < 128 * 128; idx += 256) {
        int j = idx >> 7;          // 0..127 (output index)
        int k = idx & 127;         // 0..127 (feature index)
        float w = (j < OUT_CLASSES) ? W[j * 256 + k]
                                    : W[(j - OUT_CLASSES) * 256 + 128 + k];
        Wt[k * WPAD + j] = w;
    }
    // Stage h tile, transposed: hs[k][n_local]
    for (int idx = tid; idx < TILE_NODES * 128; idx += 256) {
        int n = idx >> 7;
        int k = idx & 127;
        int node = n0 + n;
        hs[k * HPAD + n] = (node < N_NODES) ? h[node * D_FEAT + k] : 0.0f;
    }
    __syncthreads();

    const int tx = tid & 15;       // output group: j = tx*8 .. tx*8+7
    const int ty = tid >> 4;       // node group:   n = ty*4 .. ty*4+3
    const int jj = tx * 8;
    const int nn = ty * 4;

    float acc[4][8];
    #pragma unroll
    for (int a = 0; a < 4; ++a)
        #pragma unroll
        for (int b = 0; b < 8; ++b) acc[a][b] = 0.0f;

    #pragma unroll 4
    for (int k = 0; k < 128; ++k) {
        const float* wrow = &Wt[k * WPAD + jj];
        float4 w0 = *(const float4*)(wrow);
        float4 w1 = *(const float4*)(wrow + 4);
        float hv0 = hs[k * HPAD + nn + 0];
        float hv1 = hs[k * HPAD + nn + 1];
        float hv2 = hs[k * HPAD + nn + 2];
        float hv3 = hs[k * HPAD + nn + 3];
        float hv[4] = {hv0, hv1, hv2, hv3};
        #pragma unroll
        for (int a = 0; a < 4; ++a) {
            acc[a][0] += hv[a] * w0.x;
            acc[a][1] += hv[a] * w0.y;
            acc[a][2] += hv[a] * w0.z;
            acc[a][3] += hv[a] * w0.w;
            acc[a][4] += hv[a] * w1.x;
            acc[a][5] += hv[a] * w1.y;
            acc[a][6] += hv[a] * w1.z;
            acc[a][7] += hv[a] * w1.w;
        }
    }

    #pragma unroll
    for (int a = 0; a < 4; ++a) {
        int node = n0 + nn + a;
        if (node < N_NODES) {
            float* dst = &g_P[(size_t)node * PDIM + jj];
            *(float4*)(dst + 0) = make_float4(acc[a][0], acc[a][1], acc[a][2], acc[a][3]);
            *(float4*)(dst + 4) = make_float4(acc[a][4], acc[a][5], acc[a][6], acc[a][7]);
        }
    }
}

// ---------------------------------------------------------------------------
// Kernel 2: edge scatter-add. One warp per edge; lane l handles cols {2l, 2l+1}
// via float2 (32 lanes * 8B = 256B coalesced per row).
// P rows are random-access but P (25.6MB) lives in L2.
// ---------------------------------------------------------------------------
__global__ __launch_bounds__(256)
void edge_scatter_kernel(const void* __restrict__ srcp,
                         const void* __restrict__ dstp,
                         const float* __restrict__ b,
                         float* __restrict__ out) {
    const int gwarp = (int)((blockIdx.x * blockDim.x + threadIdx.x) >> 5);
    const int lane  = threadIdx.x & 31;
    if (gwarp >= N_EDGES) return;

    long long s, d;
    if (g_idx_is64) {
        s = __ldg(&((const long long*)srcp)[gwarp]);
        d = __ldg(&((const long long*)dstp)[gwarp]);
    } else {
        s = __ldg(&((const int*)srcp)[gwarp]);
        d = __ldg(&((const int*)dstp)[gwarp]);
    }

    float2 bv = *(const float2*)&b[lane * 2];
    float2 pu = *(const float2*)&g_P[(size_t)s * PDIM + lane * 2];
    float2 pv = *(const float2*)&g_P[(size_t)d * PDIM + OUT_CLASSES + lane * 2];

    float2 r;
    r.x = pu.x + pv.x + bv.x;
    r.y = pu.y + pv.y + bv.y;
    *(float2*)&out[(size_t)gwarp * OUT_CLASSES + lane * 2] = r;
}

// ---------------------------------------------------------------------------
// Launch. Inputs (metadata order): h[50000*128] f32, src[500000], dst[500000],
// W[64*256] f32, b[64] f32. Output: f32[500000*64].
// ---------------------------------------------------------------------------
extern "C" void kernel_launch(void* const* d_in, const int* in_sizes, int n_in,
                              void* d_out, int out_size) {
    const float* h   = (const float*)d_in[0];
    const void*  src = d_in[1];
    const void*  dst = d_in[2];
    const float* W   = (const float*)d_in[3];
    const float* b   = (const float*)d_in[4];
    float* out = (float*)d_out;

    (void)in_sizes; (void)n_in; (void)out_size;

    // Dynamic smem: Wt[128][132] + hs[128][65]
    const int smem_bytes = (128 * WPAD + 128 * HPAD) * (int)sizeof(float);
    cudaFuncSetAttribute(node_gemm_kernel,
                         cudaFuncAttributeMaxDynamicSharedMemorySize, smem_bytes);

    probe_idx_kernel<<<1, 1>>>(src);

    const int gemm_blocks = (N_NODES + TILE_NODES - 1) / TILE_NODES;   // 782
    node_gemm_kernel<<<gemm_blocks, 256, smem_bytes>>>(h, W);

    const int warps_needed = N_EDGES;                 // 1 warp per edge
    const int threads = 256;                          // 8 warps per block
    const int scat_blocks = (warps_needed + 7) / 8;   // 62500
    edge_scatter_kernel<<<scat_blocks, threads>>>(src, dst, b, out);
}

// round 2
// speedup vs baseline: 1.8674x; 1.8674x over previous
#include <cuda_runtime.h>
#include <stdint.h>

#define N_NODES     50000
#define N_EDGES     500000
#define D_FEAT      128
#define OUT_CLASSES 64
#define PDIM        128   // [0:64) = Pu, [64:128) = Pv

// Scratch: per-node projections. 50000*128*4B = 25.6 MB (fits in 126MB L2).
__device__ __align__(16) float g_P[N_NODES * PDIM];

// ---------------------------------------------------------------------------
// Kernel 1: node projection GEMM with 3xTF32 tensor-core path.
//   P[n][j] = sum_k h[n][k] * Wn[j][k]
// where Wn[j][k] = (j<64) ? W[j][k] : W[j-64][128+k]   (W is [64][256] row-major)
//
// Per CTA: 64 nodes x 128 outputs, 256 threads (8 warps), warp tile 32m x 32n.
// mma.sync.m16n8k8.tf32 with hi/lo split: d += ah*bh + al*bh + ah*bl
// (error ~2^-22 => fp32-grade accuracy, no precision gamble).
// smem: hs[64][132] + wn[128][132] = 101,376 B -> 2 CTAs/SM.
// Stride 132 (mod 32 == 4) makes all fragment LDS patterns bank-conflict-free.
// ---------------------------------------------------------------------------
#define GM      64
#define GSTRIDE 132
#define GEMM_SMEM ((64 + 128) * GSTRIDE * 4)

__device__ __forceinline__ uint32_t f2tf32(float x) {
    uint32_t r;
    asm("cvt.rna.tf32.f32 %0, %1;" : "=r"(r) : "f"(x));
    return r;
}
__device__ __forceinline__ void split_tf32(float x, uint32_t& hi, uint32_t& lo) {
    hi = f2tf32(x);
    lo = f2tf32(x - __uint_as_float(hi));
}
__device__ __forceinline__ void mma_tf32(float d[4], const uint32_t a[4], const uint32_t b[2]) {
    asm volatile(
        "mma.sync.aligned.m16n8k8.row.col.f32.tf32.tf32.f32 "
        "{%0,%1,%2,%3}, {%4,%5,%6,%7}, {%8,%9}, {%0,%1,%2,%3};\n"
        : "+f"(d[0]), "+f"(d[1]), "+f"(d[2]), "+f"(d[3])
        : "r"(a[0]), "r"(a[1]), "r"(a[2]), "r"(a[3]), "r"(b[0]), "r"(b[1]));
}

__global__ __launch_bounds__(256, 2)
void node_gemm_tf32(const float* __restrict__ h,
                    const float* __restrict__ W) {
    extern __shared__ float sh[];
    float* hs = sh;                    // [64][GSTRIDE]  node-major, k inner
    float* wn = sh + 64 * GSTRIDE;     // [128][GSTRIDE] out-major,  k inner

    const int tid = threadIdx.x;
    const int n0  = blockIdx.x * GM;

    // Stage h tile (64 x 128 f32) via float4
    for (int idx = tid; idx < 64 * 32; idx += 256) {
        int r = idx >> 5, c = idx & 31;
        int node = n0 + r;
        float4 v = make_float4(0.f, 0.f, 0.f, 0.f);
        if (node < N_NODES) v = __ldg((const float4*)&h[(size_t)node * D_FEAT + c * 4]);
        *(float4*)&hs[r * GSTRIDE + c * 4] = v;
    }
    // Stage Wn (128 x 128 f32): row j is contiguous in W
    for (int idx = tid; idx < 128 * 32; idx += 256) {
        int j = idx >> 5, c = idx & 31;
        const float* srcw = (j < OUT_CLASSES)
            ? &W[(size_t)j * 256 + c * 4]
            : &W[(size_t)(j - OUT_CLASSES) * 256 + 128 + c * 4];
        *(float4*)&wn[j * GSTRIDE + c * 4] = __ldg((const float4*)srcw);
    }
    __syncthreads();

    const int wid    = tid >> 5;
    const int lane   = tid & 31;
    const int warp_m = wid & 1;        // 2 warps over 64 m
    const int warp_n = wid >> 1;       // 4 warps over 128 n
    const int m_base = warp_m * 32;
    const int n_base = warp_n * 32;
    const int lr = lane >> 2;          // 0..7
    const int lc = lane & 3;           // 0..3

    float acc[2][4][4];
    #pragma unroll
    for (int a = 0; a < 2; ++a)
        #pragma unroll
        for (int b = 0; b < 4; ++b)
            #pragma unroll
            for (int c = 0; c < 4; ++c) acc[a][b][c] = 0.0f;

    #pragma unroll 2
    for (int kc = 0; kc < 16; ++kc) {
        const int k0 = kc * 8;

        uint32_t ahi[2][4], alo[2][4];
        #pragma unroll
        for (int am = 0; am < 2; ++am) {
            int r0 = m_base + am * 16 + lr;
            float x0 = hs[(r0    ) * GSTRIDE + k0 + lc];
            float x1 = hs[(r0 + 8) * GSTRIDE + k0 + lc];
            float x2 = hs[(r0    ) * GSTRIDE + k0 + lc + 4];
            float x3 = hs[(r0 + 8) * GSTRIDE + k0 + lc + 4];
            split_tf32(x0, ahi[am][0], alo[am][0]);
            split_tf32(x1, ahi[am][1], alo[am][1]);
            split_tf32(x2, ahi[am][2], alo[am][2]);
            split_tf32(x3, ahi[am][3], alo[am][3]);
        }
        uint32_t bhi[4][2], blo[4][2];
        #pragma unroll
        for (int bn = 0; bn < 4; ++bn) {
            int n = n_base + bn * 8 + lr;
            float y0 = wn[n * GSTRIDE + k0 + lc];
            float y1 = wn[n * GSTRIDE + k0 + lc + 4];
            split_tf32(y0, bhi[bn][0], blo[bn][0]);
            split_tf32(y1, bhi[bn][1], blo[bn][1]);
        }
        #pragma unroll
        for (int am = 0; am < 2; ++am)
            #pragma unroll
            for (int bn = 0; bn < 4; ++bn) {
                mma_tf32(acc[am][bn], ahi[am], bhi[bn]);
                mma_tf32(acc[am][bn], alo[am], bhi[bn]);
                mma_tf32(acc[am][bn], ahi[am], blo[bn]);
            }
    }

    // Epilogue: write P rows. c0,c1 -> (row, 2lc..2lc+1); c2,c3 -> row+8.
    #pragma unroll
    for (int am = 0; am < 2; ++am) {
        int row = m_base + am * 16 + lr;
        #pragma unroll
        for (int bn = 0; bn < 4; ++bn) {
            int j = n_base + bn * 8 + 2 * lc;
            int node = n0 + row;
            if (node < N_NODES) {
                float2 v0 = make_float2(acc[am][bn][0], acc[am][bn][1]);
                *(float2*)&g_P[(size_t)node * PDIM + j] = v0;
            }
            int node2 = n0 + row + 8;
            if (node2 < N_NODES) {
                float2 v1 = make_float2(acc[am][bn][2], acc[am][bn][3]);
                *(float2*)&g_P[(size_t)node2 * PDIM + j] = v1;
            }
        }
    }
}

// ---------------------------------------------------------------------------
// Kernel 2: edge scatter. 2 edges per warp, float4 lanes:
//   lanes 0-15 -> edge e0, lanes 16-31 -> edge e1; lane handles cols sub*4..+3.
// Output written with streaming stores (__stcs) so the 128MB stream doesn't
// evict P from L2; P reads stay L2 hits.
// int64-vs-int32 index dtype detected once per block (thread 0, 8 probes).
// ---------------------------------------------------------------------------
__global__ __launch_bounds__(256)
void edge_scatter_kernel(const void* __restrict__ srcp,
                         const void* __restrict__ dstp,
                         const float* __restrict__ b,
                         float* __restrict__ out) {
    __shared__ int s_is64;
    if (threadIdx.x == 0) {
        const long long* s64 = (const long long*)srcp;
        int ok = 1;
        #pragma unroll
        for (int i = 0; i < 8; ++i) {
            long long v = s64[i];
            if (v < 0 || v >= (long long)N_NODES) ok = 0;
        }
        s_is64 = ok;
    }
    __syncthreads();
    const int is64 = s_is64;

    const int warp = threadIdx.x >> 5;
    const int lane = threadIdx.x & 31;
    const int half = lane >> 4;          // which edge in the warp
    const int sub  = lane & 15;          // column group: cols sub*4..sub*4+3
    const long long e = (long long)blockIdx.x * 16 + warp * 2 + half;
    if (e >= N_EDGES) return;

    long long s, d;
    if (is64) {
        s = __ldg(&((const long long*)srcp)[e]);
        d = __ldg(&((const long long*)dstp)[e]);
    } else {
        s = __ldg(&((const int*)srcp)[e]);
        d = __ldg(&((const int*)dstp)[e]);
    }

    float4 bv = __ldg((const float4*)&b[sub * 4]);
    float4 pu = *(const float4*)&g_P[(size_t)s * PDIM + sub * 4];
    float4 pv = *(const float4*)&g_P[(size_t)d * PDIM + OUT_CLASSES + sub * 4];

    float4 r;
    r.x = pu.x + pv.x + bv.x;
    r.y = pu.y + pv.y + bv.y;
    r.z = pu.z + pv.z + bv.z;
    r.w = pu.w + pv.w + bv.w;
    __stcs((float4*)&out[(size_t)e * OUT_CLASSES + sub * 4], r);
}

// ---------------------------------------------------------------------------
// Launch. Inputs: h[50000*128] f32, src[500000], dst[500000],
// W[64*256] f32, b[64] f32. Output: f32[500000*64].
// ---------------------------------------------------------------------------
extern "C" void kernel_launch(void* const* d_in, const int* in_sizes, int n_in,
                              void* d_out, int out_size) {
    const float* h   = (const float*)d_in[0];
    const void*  src = d_in[1];
    const void*  dst = d_in[2];
    const float* W   = (const float*)d_in[3];
    const float* b   = (const float*)d_in[4];
    float* out = (float*)d_out;
    (void)in_sizes; (void)n_in; (void)out_size;

    cudaFuncSetAttribute(node_gemm_tf32,
                         cudaFuncAttributeMaxDynamicSharedMemorySize, GEMM_SMEM);

    const int gemm_blocks = (N_NODES + GM - 1) / GM;   // 782
    node_gemm_tf32<<<gemm_blocks, 256, GEMM_SMEM>>>(h, W);

    // 16 edges per block (8 warps x 2), 500000/16 = 31250 blocks exactly
    const int scat_blocks = (N_EDGES + 15) / 16;
    edge_scatter_kernel<<<scat_blocks, 256>>>(src, dst, b, out);
}

// round 4
// speedup vs baseline: 2.2615x; 1.2110x over previous
#include <cuda_runtime.h>
#include <stdint.h>

#define N_NODES     50000
#define N_EDGES     500000
#define D_FEAT      128
#define OUT_CLASSES 64
#define PDIM        128   // [0:64) = Pu (+bias folded), [64:128) = Pv

// Per-node projections; 25.6 MB, L2-resident.
__device__ __align__(16) float g_P[N_NODES * PDIM];

// ---------------------------------------------------------------------------
// 3xTF32 helpers (legacy mma.sync — tcgen05 is unavailable: the harness
// compiles PTX at compute_103, which rejects all tcgen05/.kind:: features).
// ---------------------------------------------------------------------------
__device__ __forceinline__ uint32_t f2tf32(float x) {
    uint32_t r;
    asm("cvt.rna.tf32.f32 %0, %1;" : "=r"(r) : "f"(x));
    return r;
}
__device__ __forceinline__ void split1(float x, float& hi, float& lo) {
    hi = __uint_as_float(f2tf32(x));
    lo = __uint_as_float(f2tf32(x - hi));
}
__device__ __forceinline__ void split4(float4 v, float4& hi, float4& lo) {
    split1(v.x, hi.x, lo.x); split1(v.y, hi.y, lo.y);
    split1(v.z, hi.z, lo.z); split1(v.w, hi.w, lo.w);
}
__device__ __forceinline__ void mma_tf32(float d[4], const uint32_t a[4], const uint32_t b[2]) {
    asm volatile(
        "mma.sync.aligned.m16n8k8.row.col.f32.tf32.tf32.f32 "
        "{%0,%1,%2,%3}, {%4,%5,%6,%7}, {%8,%9}, {%0,%1,%2,%3};\n"
        : "+f"(d[0]), "+f"(d[1]), "+f"(d[2]), "+f"(d[3])
        : "r"(a[0]), "r"(a[1]), "r"(a[2]), "r"(a[3]), "r"(b[0]), "r"(b[1]));
}

// ---------------------------------------------------------------------------
// Kernel 1: node projection GEMM, 3xTF32 with splits precomputed at staging.
//   P[n][j] = sum_k h[n][k] * Wn[j][k] (+ b[j] for j<64)
//   Wn[j][k] = (j<64) ? W[j][k] : W[j-64][128+k]
//
// Tile: 64 nodes x 128 outputs; K=128 processed in two 64-wide halves so the
// four split tiles (Ahi/Alo 64x68, Bhi/Blo 128x68) fit in 104.4KB smem
// -> 2 CTAs/SM (208.9KB of 228KB). Stride 68 (mod 32 == 4): fragment LDS
// (8 rows x cols {lc, lc+4}) hits 32 distinct banks.
// Inner loop per k8-chunk: 32 LDS + 24 MMA, no cvt (vs 88 slots in round 2).
// ---------------------------------------------------------------------------
#define GM   64
#define KH   64
#define ST   68
#define OFF_AHI 0
#define OFF_ALO (64 * ST)
#define OFF_BHI (2 * 64 * ST)
#define OFF_BLO (2 * 64 * ST + 128 * ST)
#define GEMM_SMEM ((2 * 64 * ST + 2 * 128 * ST) * 4)   // 104,448 B

__global__ __launch_bounds__(256, 2)
void node_gemm_tf32(const float* __restrict__ h,
                    const float* __restrict__ W,
                    const float* __restrict__ b) {
    extern __shared__ float sh[];
    float* Ahi = sh + OFF_AHI;
    float* Alo = sh + OFF_ALO;
    float* Bhi = sh + OFF_BHI;
    float* Blo = sh + OFF_BLO;

    const int tid = threadIdx.x;
    const int n0  = blockIdx.x * GM;

    const int wid    = tid >> 5;
    const int lane   = tid & 31;
    const int warp_m = wid & 1;        // 2 warps over 64 m
    const int warp_n = wid >> 1;       // 4 warps over 128 n
    const int m_base = warp_m * 32;
    const int n_base = warp_n * 32;
    const int lr = lane >> 2;          // 0..7
    const int lc = lane & 3;           // 0..3

    float acc[2][4][4];
    #pragma unroll
    for (int a = 0; a < 2; ++a)
        #pragma unroll
        for (int bn = 0; bn < 4; ++bn)
            #pragma unroll
            for (int c = 0; c < 4; ++c) acc[a][bn][c] = 0.0f;

    for (int half = 0; half < 2; ++half) {
        if (half) __syncthreads();     // previous compute done before restage

        // Stage A (h tile, 64 x 64 f32) split into hi/lo
        #pragma unroll
        for (int it = 0; it < 4; ++it) {
            int idx = tid + it * 256;          // 0..1023
            int r = idx >> 4;
            int k = (idx & 15) << 2;
            int node = n0 + r;
            float4 v = make_float4(0.f, 0.f, 0.f, 0.f);
            if (node < N_NODES)
                v = __ldg((const float4*)&h[(size_t)node * D_FEAT + half * KH + k]);
            float4 hi, lo; split4(v, hi, lo);
            *(float4*)&Ahi[r * ST + k] = hi;
            *(float4*)&Alo[r * ST + k] = lo;
        }
        // Stage B (Wn tile, 128 x 64 f32) split into hi/lo
        #pragma unroll
        for (int it = 0; it < 8; ++it) {
            int idx = tid + it * 256;          // 0..2047
            int j = idx >> 4;
            int k = (idx & 15) << 2;
            const float* ws = (j < OUT_CLASSES)
                ? &W[(size_t)j * 256 + half * KH + k]
                : &W[(size_t)(j - OUT_CLASSES) * 256 + 128 + half * KH + k];
            float4 v = __ldg((const float4*)ws);
            float4 hi, lo; split4(v, hi, lo);
            *(float4*)&Bhi[j * ST + k] = hi;
            *(float4*)&Blo[j * ST + k] = lo;
        }
        __syncthreads();

        #pragma unroll
        for (int kc = 0; kc < 8; ++kc) {
            const int k0 = kc * 8;

            uint32_t ahi[2][4], alo[2][4];
            #pragma unroll
            for (int am = 0; am < 2; ++am) {
                int r0 = (m_base + am * 16 + lr) * ST + k0 + lc;
                ahi[am][0] = __float_as_uint(Ahi[r0]);
                ahi[am][1] = __float_as_uint(Ahi[r0 + 8 * ST]);
                ahi[am][2] = __float_as_uint(Ahi[r0 + 4]);
                ahi[am][3] = __float_as_uint(Ahi[r0 + 8 * ST + 4]);
                alo[am][0] = __float_as_uint(Alo[r0]);
                alo[am][1] = __float_as_uint(Alo[r0 + 8 * ST]);
                alo[am][2] = __float_as_uint(Alo[r0 + 4]);
                alo[am][3] = __float_as_uint(Alo[r0 + 8 * ST + 4]);
            }
            uint32_t bhi[4][2], blo[4][2];
            #pragma unroll
            for (int bn = 0; bn < 4; ++bn) {
                int nb = (n_base + bn * 8 + lr) * ST + k0 + lc;
                bhi[bn][0] = __float_as_uint(Bhi[nb]);
                bhi[bn][1] = __float_as_uint(Bhi[nb + 4]);
                blo[bn][0] = __float_as_uint(Blo[nb]);
                blo[bn][1] = __float_as_uint(Blo[nb + 4]);
            }
            #pragma unroll
            for (int am = 0; am < 2; ++am)
                #pragma unroll
                for (int bn = 0; bn < 4; ++bn) {
                    mma_tf32(acc[am][bn], ahi[am], bhi[bn]);
                    mma_tf32(acc[am][bn], alo[am], bhi[bn]);
                    mma_tf32(acc[am][bn], ahi[am], blo[bn]);
                }
        }
    }

    // Epilogue: c0,c1 -> (row, 2lc..2lc+1); c2,c3 -> row+8.
    // Fold bias into Pu columns (warp_n 0,1 cover j < 64 entirely).
    #pragma unroll
    for (int am = 0; am < 2; ++am) {
        int row = m_base + am * 16 + lr;
        #pragma unroll
        for (int bn = 0; bn < 4; ++bn) {
            int j = n_base + bn * 8 + 2 * lc;
            float bx = 0.f, by = 0.f;
            if (warp_n < 2) {             // j in [0,64): bias columns
                float2 bv = __ldg((const float2*)&b[j]);
                bx = bv.x; by = bv.y;
            }
            int node = n0 + row;
            if (node < N_NODES) {
                float2 v0 = make_float2(acc[am][bn][0] + bx, acc[am][bn][1] + by);
                *(float2*)&g_P[(size_t)node * PDIM + j] = v0;
            }
            int node2 = n0 + row + 8;
            if (node2 < N_NODES) {
                float2 v1 = make_float2(acc[am][bn][2] + bx, acc[am][bn][3] + by);
                *(float2*)&g_P[(size_t)node2 * PDIM + j] = v1;
            }
        }
    }
}

// ---------------------------------------------------------------------------
// Kernel 2: edge scatter, bias already folded into Pu.
// 4 edges per warp: half-warps own edges (wbase+half, wbase+2+half); all
// index loads and all 4 float4 gathers issued before any use (MLP=4+).
// Streaming stores keep the 128MB output from evicting P out of L2.
// ---------------------------------------------------------------------------
__global__ __launch_bounds__(256)
void edge_scatter_kernel(const void* __restrict__ srcp,
                         const void* __restrict__ dstp,
                         float* __restrict__ out) {
    __shared__ int s_is64;
    if (threadIdx.x == 0) {
        const long long* s64 = (const long long*)srcp;
        int ok = 1;
        #pragma unroll
        for (int i = 0; i < 8; ++i) {
            long long v = s64[i];
            if (v < 0 || v >= (long long)N_NODES) ok = 0;
        }
        s_is64 = ok;
    }
    __syncthreads();
    const int is64 = s_is64;

    const int warp = threadIdx.x >> 5;
    const int lane = threadIdx.x & 31;
    const int half = lane >> 4;
    const int sub  = lane & 15;
    const long long wbase = ((long long)blockIdx.x * 8 + warp) * 4;
    const long long eA = wbase + half;
    const long long eB = wbase + 2 + half;

    long long sA, dA, sB, dB;
    if (is64) {
        const long long* s64 = (const long long*)srcp;
        const long long* d64 = (const long long*)dstp;
        sA = __ldg(&s64[eA]); dA = __ldg(&d64[eA]);
        sB = __ldg(&s64[eB]); dB = __ldg(&d64[eB]);
    } else {
        const int* s32 = (const int*)srcp;
        const int* d32 = (const int*)dstp;
        sA = __ldg(&s32[eA]); dA = __ldg(&d32[eA]);
        sB = __ldg(&s32[eB]); dB = __ldg(&d32[eB]);
    }

    float4 a0 = *(const float4*)&g_P[(size_t)sA * PDIM + sub * 4];
    float4 a1 = *(const float4*)&g_P[(size_t)dA * PDIM + OUT_CLASSES + sub * 4];
    float4 b0 = *(const float4*)&g_P[(size_t)sB * PDIM + sub * 4];
    float4 b1 = *(const float4*)&g_P[(size_t)dB * PDIM + OUT_CLASSES + sub * 4];

    float4 rA, rB;
    rA.x = a0.x + a1.x; rA.y = a0.y + a1.y; rA.z = a0.z + a1.z; rA.w = a0.w + a1.w;
    rB.x = b0.x + b1.x; rB.y = b0.y + b1.y; rB.z = b0.z + b1.z; rB.w = b0.w + b1.w;
    __stcs((float4*)&out[(size_t)eA * OUT_CLASSES + sub * 4], rA);
    __stcs((float4*)&out[(size_t)eB * OUT_CLASSES + sub * 4], rB);
}

// ---------------------------------------------------------------------------
// Launch. Inputs: h[50000*128] f32, src[500000], dst[500000],
// W[64*256] f32, b[64] f32. Output: f32[500000*64].
// ---------------------------------------------------------------------------
extern "C" void kernel_launch(void* const* d_in, const int* in_sizes, int n_in,
                              void* d_out, int out_size) {
    const float* h   = (const float*)d_in[0];
    const void*  src = d_in[1];
    const void*  dst = d_in[2];
    const float* W   = (const float*)d_in[3];
    const float* b   = (const float*)d_in[4];
    float* out = (float*)d_out;
    (void)in_sizes; (void)n_in; (void)out_size;

    cudaFuncSetAttribute(node_gemm_tf32,
                         cudaFuncAttributeMaxDynamicSharedMemorySize, GEMM_SMEM);

    const int gemm_blocks = (N_NODES + GM - 1) / GM;   // 782
    node_gemm_tf32<<<gemm_blocks, 256, GEMM_SMEM>>>(h, W, b);

    // 32 edges per block (8 warps x 4): 500000/32 = 15625 exactly
    edge_scatter_kernel<<<N_EDGES / 32, 256>>>(src, dst, out);
}

// round 5
// speedup vs baseline: 2.5879x; 1.1444x over previous
#include <cuda_runtime.h>
#include <stdint.h>

#define N_NODES     50000
#define N_EDGES     500000
#define D_FEAT      128
#define OUT_CLASSES 64
#define PDIM        128   // [0:64) = Pu (+bias folded), [64:128) = Pv

// Per-node projections; 25.6 MB, L2-resident.
__device__ __align__(16) float g_P[N_NODES * PDIM];

// ---------------------------------------------------------------------------
// 3xBF16 helpers (legacy mma.sync — tcgen05 unavailable at compute_103).
// fp32 x split as x = hi + lo (bf16 each, captures ~17 mantissa bits).
// P = ahi*bhi + alo*bhi + ahi*blo; dropped alo*blo ~ 2^-18.
// ---------------------------------------------------------------------------
__device__ __forceinline__ void split_pair(float x0, float x1,
                                           uint32_t& hi, uint32_t& lo) {
    // pack: bits[15:0] = bf16(x0) (even k), bits[31:16] = bf16(x1) (odd k)
    asm("cvt.rn.bf16x2.f32 %0, %1, %2;" : "=r"(hi) : "f"(x1), "f"(x0));
    float h0 = __uint_as_float(hi << 16);
    float h1 = __uint_as_float(hi & 0xFFFF0000u);
    asm("cvt.rn.bf16x2.f32 %0, %1, %2;" : "=r"(lo) : "f"(x1 - h1), "f"(x0 - h0));
}
__device__ __forceinline__ void mma_bf16(float d[4], const uint32_t a[4], const uint32_t b[2]) {
    asm volatile(
        "mma.sync.aligned.m16n8k16.row.col.f32.bf16.bf16.f32 "
        "{%0,%1,%2,%3}, {%4,%5,%6,%7}, {%8,%9}, {%0,%1,%2,%3};\n"
        : "+f"(d[0]), "+f"(d[1]), "+f"(d[2]), "+f"(d[3])
        : "r"(a[0]), "r"(a[1]), "r"(a[2]), "r"(a[3]), "r"(b[0]), "r"(b[1]));
}

// ---------------------------------------------------------------------------
// Kernel 1: node projection GEMM, 3xBF16.
//   P[n][j] = sum_k h[n][k] * Wn[j][k] (+ b[j] for j<64)
//   Wn[j][k] = (j<64) ? W[j][k] : W[j-64][128+k]
//
// Tile: 64 nodes x 128 outputs x K=128 (single staging phase).
// smem (uint32 = bf16x2 pairs, k-major, stride 68):
//   Ahi/Alo: 64 x 68, Bhi/Blo: 128 x 68  -> 104,448 B, 2 CTAs/SM.
// Stride 68 (mod 32 == 4): fragment LDS (8 rows x pair {lc, lc+4}) hits all
// 32 banks. Inner loop per k16-chunk: 32 LDS + 24 MMA; 8 chunks total.
// ---------------------------------------------------------------------------
#define GM   64
#define ST   68   // uint32 units per row (64 pairs + 4 pad)
#define OFF_AHI 0
#define OFF_ALO (64 * ST)
#define OFF_BHI (2 * 64 * ST)
#define OFF_BLO (2 * 64 * ST + 128 * ST)
#define GEMM_SMEM ((2 * 64 * ST + 2 * 128 * ST) * 4)   // 104,448 B

__global__ __launch_bounds__(256, 2)
void node_gemm_bf16(const float* __restrict__ h,
                    const float* __restrict__ W,
                    const float* __restrict__ b,
                    int node_off) {
    extern __shared__ uint32_t sh[];
    uint32_t* Ahi = sh + OFF_AHI;
    uint32_t* Alo = sh + OFF_ALO;
    uint32_t* Bhi = sh + OFF_BHI;
    uint32_t* Blo = sh + OFF_BLO;

    const int tid = threadIdx.x;
    const int n0  = node_off + blockIdx.x * GM;

    // Stage A (h tile, 64 x 128 f32 -> bf16x2 hi/lo)
    #pragma unroll
    for (int it = 0; it < 8; ++it) {
        int idx = tid + it * 256;          // 0..2047
        int r  = idx >> 5;                 // 0..63
        int c4 = idx & 31;                 // float4 index; k = c4*4
        int node = n0 + r;
        float4 v = make_float4(0.f, 0.f, 0.f, 0.f);
        if (node < N_NODES)
            v = __ldg((const float4*)&h[(size_t)node * D_FEAT + c4 * 4]);
        uint32_t h0, l0, h1, l1;
        split_pair(v.x, v.y, h0, l0);
        split_pair(v.z, v.w, h1, l1);
        int p = r * ST + c4 * 2;
        *(uint2*)&Ahi[p] = make_uint2(h0, h1);
        *(uint2*)&Alo[p] = make_uint2(l0, l1);
    }
    // Stage B (Wn tile, 128 x 128 f32 -> bf16x2 hi/lo)
    #pragma unroll
    for (int it = 0; it < 16; ++it) {
        int idx = tid + it * 256;          // 0..4095
        int j  = idx >> 5;                 // 0..127
        int c4 = idx & 31;
        const float* ws = (j < OUT_CLASSES)
            ? &W[(size_t)j * 256 + c4 * 4]
            : &W[(size_t)(j - OUT_CLASSES) * 256 + 128 + c4 * 4];
        float4 v = __ldg((const float4*)ws);
        uint32_t h0, l0, h1, l1;
        split_pair(v.x, v.y, h0, l0);
        split_pair(v.z, v.w, h1, l1);
        int p = j * ST + c4 * 2;
        *(uint2*)&Bhi[p] = make_uint2(h0, h1);
        *(uint2*)&Blo[p] = make_uint2(l0, l1);
    }
    __syncthreads();

    const int wid    = tid >> 5;
    const int lane   = tid & 31;
    const int warp_m = wid & 1;        // 2 warps over 64 m
    const int warp_n = wid >> 1;       // 4 warps over 128 n
    const int m_base = warp_m * 32;
    const int n_base = warp_n * 32;
    const int lr = lane >> 2;          // 0..7 (row / n-col group)
    const int lc = lane & 3;           // 0..3 (k-pair group)

    float acc[2][4][4];
    #pragma unroll
    for (int a = 0; a < 2; ++a)
        #pragma unroll
        for (int bn = 0; bn < 4; ++bn)
            #pragma unroll
            for (int c = 0; c < 4; ++c) acc[a][bn][c] = 0.0f;

    #pragma unroll 2
    for (int kc = 0; kc < 8; ++kc) {
        const int p0 = kc * 8;          // pair offset of this k16 chunk

        uint32_t ah[2][4], al[2][4];
        #pragma unroll
        for (int am = 0; am < 2; ++am) {
            int base = (m_base + am * 16 + lr) * ST + p0 + lc;
            ah[am][0] = Ahi[base];
            ah[am][1] = Ahi[base + 8 * ST];
            ah[am][2] = Ahi[base + 4];
            ah[am][3] = Ahi[base + 8 * ST + 4];
            al[am][0] = Alo[base];
            al[am][1] = Alo[base + 8 * ST];
            al[am][2] = Alo[base + 4];
            al[am][3] = Alo[base + 8 * ST + 4];
        }
        uint32_t bh[4][2], bl[4][2];
        #pragma unroll
        for (int bn = 0; bn < 4; ++bn) {
            int nb = (n_base + bn * 8 + lr) * ST + p0 + lc;
            bh[bn][0] = Bhi[nb];
            bh[bn][1] = Bhi[nb + 4];
            bl[bn][0] = Blo[nb];
            bl[bn][1] = Blo[nb + 4];
        }
        #pragma unroll
        for (int am = 0; am < 2; ++am)
            #pragma unroll
            for (int bn = 0; bn < 4; ++bn) {
                mma_bf16(acc[am][bn], ah[am], bh[bn]);
                mma_bf16(acc[am][bn], al[am], bh[bn]);
                mma_bf16(acc[am][bn], ah[am], bl[bn]);
            }
    }

    // Epilogue: c0,c1 -> (row, 2lc..2lc+1); c2,c3 -> row+8.
    // Fold bias into Pu columns (warp_n 0,1 cover j < 64 entirely).
    #pragma unroll
    for (int am = 0; am < 2; ++am) {
        int row = m_base + am * 16 + lr;
        #pragma unroll
        for (int bn = 0; bn < 4; ++bn) {
            int j = n_base + bn * 8 + 2 * lc;
            float bx = 0.f, by = 0.f;
            if (warp_n < 2) {             // j in [0,64): bias columns
                float2 bv = __ldg((const float2*)&b[j]);
                bx = bv.x; by = bv.y;
            }
            int node = n0 + row;
            if (node < N_NODES) {
                float2 v0 = make_float2(acc[am][bn][0] + bx, acc[am][bn][1] + by);
                *(float2*)&g_P[(size_t)node * PDIM + j] = v0;
            }
            int node2 = n0 + row + 8;
            if (node2 < N_NODES) {
                float2 v1 = make_float2(acc[am][bn][2] + bx, acc[am][bn][3] + by);
                *(float2*)&g_P[(size_t)node2 * PDIM + j] = v1;
            }
        }
    }
}

// ---------------------------------------------------------------------------
// Kernel 2: edge scatter, bias already folded into Pu. L2-throughput bound
// (384MB through LTS ~= 32us floor); 4 edges/warp, front-batched gathers,
// streaming stores for the 128MB output.
// ---------------------------------------------------------------------------
__global__ __launch_bounds__(256)
void edge_scatter_kernel(const void* __restrict__ srcp,
                         const void* __restrict__ dstp,
                         float* __restrict__ out) {
    __shared__ int s_is64;
    if (threadIdx.x == 0) {
        const long long* s64 = (const long long*)srcp;
        int ok = 1;
        #pragma unroll
        for (int i = 0; i < 8; ++i) {
            long long v = s64[i];
            if (v < 0 || v >= (long long)N_NODES) ok = 0;
        }
        s_is64 = ok;
    }
    __syncthreads();
    const int is64 = s_is64;

    const int warp = threadIdx.x >> 5;
    const int lane = threadIdx.x & 31;
    const int half = lane >> 4;
    const int sub  = lane & 15;
    const long long wbase = ((long long)blockIdx.x * 8 + warp) * 4;
    const long long eA = wbase + half;
    const long long eB = wbase + 2 + half;

    long long sA, dA, sB, dB;
    if (is64) {
        const long long* s64 = (const long long*)srcp;
        const long long* d64 = (const long long*)dstp;
        sA = __ldg(&s64[eA]); dA = __ldg(&d64[eA]);
        sB = __ldg(&s64[eB]); dB = __ldg(&d64[eB]);
    } else {
        const int* s32 = (const int*)srcp;
        const int* d32 = (const int*)dstp;
        sA = __ldg(&s32[eA]); dA = __ldg(&d32[eA]);
        sB = __ldg(&s32[eB]); dB = __ldg(&d32[eB]);
    }

    float4 a0 = *(const float4*)&g_P[(size_t)sA * PDIM + sub * 4];
    float4 a1 = *(const float4*)&g_P[(size_t)dA * PDIM + OUT_CLASSES + sub * 4];
    float4 b0 = *(const float4*)&g_P[(size_t)sB * PDIM + sub * 4];
    float4 b1 = *(const float4*)&g_P[(size_t)dB * PDIM + OUT_CLASSES + sub * 4];

    float4 rA, rB;
    rA.x = a0.x + a1.x; rA.y = a0.y + a1.y; rA.z = a0.z + a1.z; rA.w = a0.w + a1.w;
    rB.x = b0.x + b1.x; rB.y = b0.y + b1.y; rB.z = b0.z + b1.z; rB.w = b0.w + b1.w;
    __stcs((float4*)&out[(size_t)eA * OUT_CLASSES + sub * 4], rA);
    __stcs((float4*)&out[(size_t)eB * OUT_CLASSES + sub * 4], rB);
}

// ---------------------------------------------------------------------------
// Launch. GEMM split into 3 node-range launches so ncu (-s 5 -c 1, 4
// launches/call) captures launch #6 = the middle GEMM chunk.
// ---------------------------------------------------------------------------
extern "C" void kernel_launch(void* const* d_in, const int* in_sizes, int n_in,
                              void* d_out, int out_size) {
    const float* h   = (const float*)d_in[0];
    const void*  src = d_in[1];
    const void*  dst = d_in[2];
    const float* W   = (const float*)d_in[3];
    const float* b   = (const float*)d_in[4];
    float* out = (float*)d_out;
    (void)in_sizes; (void)n_in; (void)out_size;

    cudaFuncSetAttribute(node_gemm_bf16,
                         cudaFuncAttributeMaxDynamicSharedMemorySize, GEMM_SMEM);

    // 782 blocks total, split 261 / 261 / 260
    node_gemm_bf16<<<261, 256, GEMM_SMEM>>>(h, W, b, 0);
    node_gemm_bf16<<<261, 256, GEMM_SMEM>>>(h, W, b, 261 * GM);
    node_gemm_bf16<<<260, 256, GEMM_SMEM>>>(h, W, b, 522 * GM);

    // 32 edges per block (8 warps x 4): 500000/32 = 15625 exactly
    edge_scatter_kernel<<<N_EDGES / 32, 256>>>(src, dst, out);
}

// round 7
// speedup vs baseline: 2.9574x; 1.1428x over previous
#include <cuda_runtime.h>
#include <stdint.h>

#define N_NODES     50000
#define N_EDGES     500000
#define D_FEAT      128
#define OUT_CLASSES 64
#define PDIM        128   // [0:64) = Pu (+bias folded), [64:128) = Pv

// Per-node projections; 25.6 MB, L2-resident.
__device__ __align__(16) float g_P[N_NODES * PDIM];
// Pre-split W in mma-fragment order: [ng(16)][kc(8)][lane(32)] x uint4
// uint4 = { bhi(pair p0), bhi(pair p0+4), blo(pair p0), blo(pair p0+4) }
// where n = ng*8 + (lane>>2), p0 = kc*8 + (lane&3), pair p = bf16x2 of
// (Wn[n][2p], Wn[n][2p+1]), Wn[j][k] = (j<64) ? W[j][k] : W[j-64][128+k].
__device__ __align__(16) uint4 g_Wfrag[16 * 8 * 32];   // 64 KB, L1/L2-resident

// ---------------------------------------------------------------------------
// 3xBF16 helpers (legacy mma.sync — tcgen05 unavailable at compute_103).
// x = hi + lo (bf16 each, ~17 mantissa bits); P = ah*bh + al*bh + ah*bl.
// (Round 7 = round 6 resubmitted verbatim after an infra device-busy flake.)
// ---------------------------------------------------------------------------
__device__ __forceinline__ void split_pair(float x0, float x1,
                                           uint32_t& hi, uint32_t& lo) {
    asm("cvt.rn.bf16x2.f32 %0, %1, %2;" : "=r"(hi) : "f"(x1), "f"(x0));
    float h0 = __uint_as_float(hi << 16);
    float h1 = __uint_as_float(hi & 0xFFFF0000u);
    asm("cvt.rn.bf16x2.f32 %0, %1, %2;" : "=r"(lo) : "f"(x1 - h1), "f"(x0 - h0));
}
__device__ __forceinline__ void mma_bf16(float d[4], const uint32_t a[4], const uint32_t b[2]) {
    asm volatile(
        "mma.sync.aligned.m16n8k16.row.col.f32.bf16.bf16.f32 "
        "{%0,%1,%2,%3}, {%4,%5,%6,%7}, {%8,%9}, {%0,%1,%2,%3};\n"
        : "+f"(d[0]), "+f"(d[1]), "+f"(d[2]), "+f"(d[3])
        : "r"(a[0]), "r"(a[1]), "r"(a[2]), "r"(a[3]), "r"(b[0]), "r"(b[1]));
}

// ---------------------------------------------------------------------------
// Kernel 0: one-shot W split into fragment order. 4096 uint4 total.
// ---------------------------------------------------------------------------
__global__ __launch_bounds__(256)
void wsplit_kernel(const float* __restrict__ W) {
    int t = blockIdx.x * 256 + threadIdx.x;     // 0..4095
    int ng   = t >> 8;
    int kc   = (t >> 5) & 7;
    int lane = t & 31;
    int lr = lane >> 2, lc = lane & 3;
    int n  = ng * 8 + lr;
    const float* wrow = (n < OUT_CLASSES)
        ? &W[(size_t)n * 256]
        : &W[(size_t)(n - OUT_CLASSES) * 256 + 128];
    int p0 = kc * 8 + lc;
    uint32_t h0, l0, h1, l1;
    split_pair(wrow[2 * p0],       wrow[2 * p0 + 1],       h0, l0);
    split_pair(wrow[2 * (p0 + 4)], wrow[2 * (p0 + 4) + 1], h1, l1);
    g_Wfrag[t] = make_uint4(h0, h1, l0, l1);
}

// ---------------------------------------------------------------------------
// Kernel 1: node projection GEMM, 3xBF16, B pre-split in g_Wfrag (L1-hit
// LDG.128 fragments), only A staged in smem.
// Tile: 64 nodes x 128 outputs x K=128. smem: Ahi/Alo 64x68 u32 = 34.8KB.
// ---------------------------------------------------------------------------
#define GM   64
#define ST   68   // uint32 per row (64 pairs + 4 pad); 68 mod 32 = 4
#define GEMM_SMEM (2 * 64 * ST * 4)   // 34,816 B

__global__ __launch_bounds__(256, 2)
void node_gemm_bf16(const float* __restrict__ h,
                    const float* __restrict__ b) {
    extern __shared__ uint32_t sh[];
    uint32_t* Ahi = sh;
    uint32_t* Alo = sh + 64 * ST;

    const int tid = threadIdx.x;
    const int n0  = blockIdx.x * GM;

    // Stage A (h tile, 64 x 128 f32 -> bf16x2 hi/lo)
    #pragma unroll
    for (int it = 0; it < 8; ++it) {
        int idx = tid + it * 256;          // 0..2047
        int r  = idx >> 5;                 // 0..63
        int c4 = idx & 31;                 // float4 index; k = c4*4
        int node = n0 + r;
        float4 v = make_float4(0.f, 0.f, 0.f, 0.f);
        if (node < N_NODES)
            v = __ldg((const float4*)&h[(size_t)node * D_FEAT + c4 * 4]);
        uint32_t h0, l0, h1, l1;
        split_pair(v.x, v.y, h0, l0);
        split_pair(v.z, v.w, h1, l1);
        int p = r * ST + c4 * 2;
        *(uint2*)&Ahi[p] = make_uint2(h0, h1);
        *(uint2*)&Alo[p] = make_uint2(l0, l1);
    }
    __syncthreads();

    const int wid    = tid >> 5;
    const int lane   = tid & 31;
    const int warp_m = wid & 1;        // 2 warps over 64 m
    const int warp_n = wid >> 1;       // 4 warps over 128 n
    const int m_base = warp_m * 32;
    const int lr = lane >> 2;          // 0..7
    const int lc = lane & 3;           // 0..3

    // Fragment base for this warp's n range: ng = warp_n*4 + bn
    const uint4* wf = &g_Wfrag[(warp_n * 4) * 8 * 32 + lane];

    float acc[2][4][4];
    #pragma unroll
    for (int a = 0; a < 2; ++a)
        #pragma unroll
        for (int bn = 0; bn < 4; ++bn)
            #pragma unroll
            for (int c = 0; c < 4; ++c) acc[a][bn][c] = 0.0f;

    #pragma unroll 2
    for (int kc = 0; kc < 8; ++kc) {
        const int p0 = kc * 8;

        // B fragments: 4 x LDG.128, warp-uniform addresses, L1-resident.
        uint4 bf[4];
        #pragma unroll
        for (int bn = 0; bn < 4; ++bn)
            bf[bn] = __ldg(&wf[(bn * 8 + kc) * 32]);

        uint32_t ah[2][4], al[2][4];
        #pragma unroll
        for (int am = 0; am < 2; ++am) {
            int base = (m_base + am * 16 + lr) * ST + p0 + lc;
            ah[am][0] = Ahi[base];
            ah[am][1] = Ahi[base + 8 * ST];
            ah[am][2] = Ahi[base + 4];
            ah[am][3] = Ahi[base + 8 * ST + 4];
            al[am][0] = Alo[base];
            al[am][1] = Alo[base + 8 * ST];
            al[am][2] = Alo[base + 4];
            al[am][3] = Alo[base + 8 * ST + 4];
        }
        #pragma unroll
        for (int am = 0; am < 2; ++am)
            #pragma unroll
            for (int bn = 0; bn < 4; ++bn) {
                uint32_t bh[2] = { bf[bn].x, bf[bn].y };
                uint32_t bl[2] = { bf[bn].z, bf[bn].w };
                mma_bf16(acc[am][bn], ah[am], bh);
                mma_bf16(acc[am][bn], al[am], bh);
                mma_bf16(acc[am][bn], ah[am], bl);
            }
    }

    // Epilogue: c0,c1 -> (row, 2lc..2lc+1); c2,c3 -> row+8. Bias in Pu cols.
    #pragma unroll
    for (int am = 0; am < 2; ++am) {
        int row = m_base + am * 16 + lr;
        #pragma unroll
        for (int bn = 0; bn < 4; ++bn) {
            int j = warp_n * 32 + bn * 8 + 2 * lc;
            float bx = 0.f, by = 0.f;
            if (warp_n < 2) {             // j in [0,64): bias columns
                float2 bv = __ldg((const float2*)&b[j]);
                bx = bv.x; by = bv.y;
            }
            int node = n0 + row;
            if (node < N_NODES) {
                float2 v0 = make_float2(acc[am][bn][0] + bx, acc[am][bn][1] + by);
                *(float2*)&g_P[(size_t)node * PDIM + j] = v0;
            }
            int node2 = n0 + row + 8;
            if (node2 < N_NODES) {
                float2 v1 = make_float2(acc[am][bn][2] + bx, acc[am][bn][3] + by);
                *(float2*)&g_P[(size_t)node2 * PDIM + j] = v1;
            }
        }
    }
}

// ---------------------------------------------------------------------------
// Kernel 2: edge scatter. At the LTS throughput floor (392MB ~ 33us);
// 4 edges/warp, front-batched gathers, streaming output stores.
// ---------------------------------------------------------------------------
__global__ __launch_bounds__(256)
void edge_scatter_kernel(const void* __restrict__ srcp,
                         const void* __restrict__ dstp,
                         float* __restrict__ out) {
    __shared__ int s_is64;
    if (threadIdx.x == 0) {
        const long long* s64 = (const long long*)srcp;
        int ok = 1;
        #pragma unroll
        for (int i = 0; i < 8; ++i) {
            long long v = s64[i];
            if (v < 0 || v >= (long long)N_NODES) ok = 0;
        }
        s_is64 = ok;
    }
    __syncthreads();
    const int is64 = s_is64;

    const int warp = threadIdx.x >> 5;
    const int lane = threadIdx.x & 31;
    const int half = lane >> 4;
    const int sub  = lane & 15;
    const long long wbase = ((long long)blockIdx.x * 8 + warp) * 4;
    const long long eA = wbase + half;
    const long long eB = wbase + 2 + half;

    long long sA, dA, sB, dB;
    if (is64) {
        const long long* s64 = (const long long*)srcp;
        const long long* d64 = (const long long*)dstp;
        sA = __ldg(&s64[eA]); dA = __ldg(&d64[eA]);
        sB = __ldg(&s64[eB]); dB = __ldg(&d64[eB]);
    } else {
        const int* s32 = (const int*)srcp;
        const int* d32 = (const int*)dstp;
        sA = __ldg(&s32[eA]); dA = __ldg(&d32[eA]);
        sB = __ldg(&s32[eB]); dB = __ldg(&d32[eB]);
    }

    float4 a0 = *(const float4*)&g_P[(size_t)sA * PDIM + sub * 4];
    float4 a1 = *(const float4*)&g_P[(size_t)dA * PDIM + OUT_CLASSES + sub * 4];
    float4 b0 = *(const float4*)&g_P[(size_t)sB * PDIM + sub * 4];
    float4 b1 = *(const float4*)&g_P[(size_t)dB * PDIM + OUT_CLASSES + sub * 4];

    float4 rA, rB;
    rA.x = a0.x + a1.x; rA.y = a0.y + a1.y; rA.z = a0.z + a1.z; rA.w = a0.w + a1.w;
    rB.x = b0.x + b1.x; rB.y = b0.y + b1.y; rB.z = b0.z + b1.z; rB.w = b0.w + b1.w;
    __stcs((float4*)&out[(size_t)eA * OUT_CLASSES + sub * 4], rA);
    __stcs((float4*)&out[(size_t)eB * OUT_CLASSES + sub * 4], rB);
}

// ---------------------------------------------------------------------------
// Launch. Inputs: h[50000*128] f32, src[500000], dst[500000],
// W[64*256] f32, b[64] f32. Output: f32[500000*64].
// ---------------------------------------------------------------------------
extern "C" void kernel_launch(void* const* d_in, const int* in_sizes, int n_in,
                              void* d_out, int out_size) {
    const float* h   = (const float*)d_in[0];
    const void*  src = d_in[1];
    const void*  dst = d_in[2];
    const float* W   = (const float*)d_in[3];
    const float* b   = (const float*)d_in[4];
    float* out = (float*)d_out;
    (void)in_sizes; (void)n_in; (void)out_size;

    wsplit_kernel<<<16, 256>>>(W);

    const int gemm_blocks = (N_NODES + GM - 1) / GM;   // 782
    node_gemm_bf16<<<gemm_blocks, 256, GEMM_SMEM>>>(h, b);

    // 32 edges per block (8 warps x 4): 500000/32 = 15625 exactly
    edge_scatter_kernel<<<N_EDGES / 32, 256>>>(src, dst, out);
}

// round 8
// speedup vs baseline: 3.2977x; 1.1151x over previous
#include <cuda_runtime.h>
#include <cuda_fp16.h>
#include <stdint.h>

#define N_NODES     50000
#define N_EDGES     500000
#define D_FEAT      128
#define OUT_CLASSES 64
#define PDIM        128   // [0:64) = Pu (+bias folded), [64:128) = Pv

// Per-node projections in fp16; 12.8 MB, L2-resident. Halves scatter traffic
// vs fp32 (score std ~1.0, fp16 quantization ~2.4e-4 norm-relative).
__device__ __align__(16) __half g_P[N_NODES * PDIM];
// Pre-split W in mma-fragment order: [ng(16)][kc(8)][lane(32)] x uint4
// uint4 = { bhi(pair p0), bhi(pair p0+4), blo(pair p0), blo(pair p0+4) }
// where n = ng*8 + (lane>>2), p0 = kc*8 + (lane&3), pair p = bf16x2 of
// (Wn[n][2p], Wn[n][2p+1]), Wn[j][k] = (j<64) ? W[j][k] : W[j-64][128+k].
__device__ __align__(16) uint4 g_Wfrag[16 * 8 * 32];   // 64 KB, L1/L2-resident

// ---------------------------------------------------------------------------
// 3xBF16 helpers (legacy mma.sync — tcgen05 unavailable at compute_103).
// x = hi + lo (bf16 each, ~17 mantissa bits); P = ah*bh + al*bh + ah*bl.
// ---------------------------------------------------------------------------
__device__ __forceinline__ void split_pair(float x0, float x1,
                                           uint32_t& hi, uint32_t& lo) {
    asm("cvt.rn.bf16x2.f32 %0, %1, %2;" : "=r"(hi) : "f"(x1), "f"(x0));
    float h0 = __uint_as_float(hi << 16);
    float h1 = __uint_as_float(hi & 0xFFFF0000u);
    asm("cvt.rn.bf16x2.f32 %0, %1, %2;" : "=r"(lo) : "f"(x1 - h1), "f"(x0 - h0));
}
__device__ __forceinline__ void mma_bf16(float d[4], const uint32_t a[4], const uint32_t b[2]) {
    asm volatile(
        "mma.sync.aligned.m16n8k16.row.col.f32.bf16.bf16.f32 "
        "{%0,%1,%2,%3}, {%4,%5,%6,%7}, {%8,%9}, {%0,%1,%2,%3};\n"
        : "+f"(d[0]), "+f"(d[1]), "+f"(d[2]), "+f"(d[3])
        : "r"(a[0]), "r"(a[1]), "r"(a[2]), "r"(a[3]), "r"(b[0]), "r"(b[1]));
}

// ---------------------------------------------------------------------------
// Kernel 0: one-shot W split into fragment order. 4096 uint4 total.
// ---------------------------------------------------------------------------
__global__ __launch_bounds__(256)
void wsplit_kernel(const float* __restrict__ W) {
    int t = blockIdx.x * 256 + threadIdx.x;     // 0..4095
    int ng   = t >> 8;
    int kc   = (t >> 5) & 7;
    int lane = t & 31;
    int lr = lane >> 2, lc = lane & 3;
    int n  = ng * 8 + lr;
    const float* wrow = (n < OUT_CLASSES)
        ? &W[(size_t)n * 256]
        : &W[(size_t)(n - OUT_CLASSES) * 256 + 128];
    int p0 = kc * 8 + lc;
    uint32_t h0, l0, h1, l1;
    split_pair(wrow[2 * p0],       wrow[2 * p0 + 1],       h0, l0);
    split_pair(wrow[2 * (p0 + 4)], wrow[2 * (p0 + 4) + 1], h1, l1);
    g_Wfrag[t] = make_uint4(h0, h1, l0, l1);
}

// ---------------------------------------------------------------------------
// Kernel 1: node projection GEMM, 3xBF16, B pre-split in g_Wfrag (L1-hit
// LDG.128 fragments), only A staged in smem. Epilogue writes fp16 P.
// Tile: 64 nodes x 128 outputs x K=128. smem: Ahi/Alo 64x68 u32 = 34.8KB.
// ---------------------------------------------------------------------------
#define GM   64
#define ST   68   // uint32 per row (64 pairs + 4 pad); 68 mod 32 = 4
#define GEMM_SMEM (2 * 64 * ST * 4)   // 34,816 B

__global__ __launch_bounds__(256, 2)
void node_gemm_bf16(const float* __restrict__ h,
                    const float* __restrict__ b) {
    extern __shared__ uint32_t sh[];
    uint32_t* Ahi = sh;
    uint32_t* Alo = sh + 64 * ST;

    const int tid = threadIdx.x;
    const int n0  = blockIdx.x * GM;

    // Stage A (h tile, 64 x 128 f32 -> bf16x2 hi/lo)
    #pragma unroll
    for (int it = 0; it < 8; ++it) {
        int idx = tid + it * 256;          // 0..2047
        int r  = idx >> 5;                 // 0..63
        int c4 = idx & 31;                 // float4 index; k = c4*4
        int node = n0 + r;
        float4 v = make_float4(0.f, 0.f, 0.f, 0.f);
        if (node < N_NODES)
            v = __ldg((const float4*)&h[(size_t)node * D_FEAT + c4 * 4]);
        uint32_t h0, l0, h1, l1;
        split_pair(v.x, v.y, h0, l0);
        split_pair(v.z, v.w, h1, l1);
        int p = r * ST + c4 * 2;
        *(uint2*)&Ahi[p] = make_uint2(h0, h1);
        *(uint2*)&Alo[p] = make_uint2(l0, l1);
    }
    __syncthreads();

    const int wid    = tid >> 5;
    const int lane   = tid & 31;
    const int warp_m = wid & 1;        // 2 warps over 64 m
    const int warp_n = wid >> 1;       // 4 warps over 128 n
    const int m_base = warp_m * 32;
    const int lr = lane >> 2;          // 0..7
    const int lc = lane & 3;           // 0..3

    // Fragment base for this warp's n range: ng = warp_n*4 + bn
    const uint4* wf = &g_Wfrag[(warp_n * 4) * 8 * 32 + lane];

    float acc[2][4][4];
    #pragma unroll
    for (int a = 0; a < 2; ++a)
        #pragma unroll
        for (int bn = 0; bn < 4; ++bn)
            #pragma unroll
            for (int c = 0; c < 4; ++c) acc[a][bn][c] = 0.0f;

    #pragma unroll 2
    for (int kc = 0; kc < 8; ++kc) {
        const int p0 = kc * 8;

        // B fragments: 4 x LDG.128, warp-uniform addresses, L1-resident.
        uint4 bf[4];
        #pragma unroll
        for (int bn = 0; bn < 4; ++bn)
            bf[bn] = __ldg(&wf[(bn * 8 + kc) * 32]);

        uint32_t ah[2][4], al[2][4];
        #pragma unroll
        for (int am = 0; am < 2; ++am) {
            int base = (m_base + am * 16 + lr) * ST + p0 + lc;
            ah[am][0] = Ahi[base];
            ah[am][1] = Ahi[base + 8 * ST];
            ah[am][2] = Ahi[base + 4];
            ah[am][3] = Ahi[base + 8 * ST + 4];
            al[am][0] = Alo[base];
            al[am][1] = Alo[base + 8 * ST];
            al[am][2] = Alo[base + 4];
            al[am][3] = Alo[base + 8 * ST + 4];
        }
        #pragma unroll
        for (int am = 0; am < 2; ++am)
            #pragma unroll
            for (int bn = 0; bn < 4; ++bn) {
                uint32_t bh[2] = { bf[bn].x, bf[bn].y };
                uint32_t bl[2] = { bf[bn].z, bf[bn].w };
                mma_bf16(acc[am][bn], ah[am], bh);
                mma_bf16(acc[am][bn], al[am], bh);
                mma_bf16(acc[am][bn], ah[am], bl);
            }
    }

    // Epilogue: c0,c1 -> (row, 2lc..2lc+1); c2,c3 -> row+8. Bias in Pu cols.
    // Convert to fp16 (half2 per column pair).
    #pragma unroll
    for (int am = 0; am < 2; ++am) {
        int row = m_base + am * 16 + lr;
        #pragma unroll
        for (int bn = 0; bn < 4; ++bn) {
            int j = warp_n * 32 + bn * 8 + 2 * lc;
            float bx = 0.f, by = 0.f;
            if (warp_n < 2) {             // j in [0,64): bias columns
                float2 bv = __ldg((const float2*)&b[j]);
                bx = bv.x; by = bv.y;
            }
            int node = n0 + row;
            if (node < N_NODES) {
                __half2 v0 = __floats2half2_rn(acc[am][bn][0] + bx,
                                               acc[am][bn][1] + by);
                *(__half2*)&g_P[(size_t)node * PDIM + j] = v0;
            }
            int node2 = n0 + row + 8;
            if (node2 < N_NODES) {
                __half2 v1 = __floats2half2_rn(acc[am][bn][2] + bx,
                                               acc[am][bn][3] + by);
                *(__half2*)&g_P[(size_t)node2 * PDIM + j] = v1;
            }
        }
    }
}

// ---------------------------------------------------------------------------
// Kernel 2: edge scatter on fp16 P rows (128 B per projection half).
// 4 edges/warp; each half-warp lane loads uint2 (4 halves) from Pu[s] and
// Pv[d] (16 lanes x 8 B = one 128 B line per row), converts, adds, writes
// float4 (256 B/edge) with streaming stores.
// ---------------------------------------------------------------------------
__global__ __launch_bounds__(256)
void edge_scatter_kernel(const void* __restrict__ srcp,
                         const void* __restrict__ dstp,
                         float* __restrict__ out) {
    __shared__ int s_is64;
    if (threadIdx.x == 0) {
        const long long* s64 = (const long long*)srcp;
        int ok = 1;
        #pragma unroll
        for (int i = 0; i < 8; ++i) {
            long long v = s64[i];
            if (v < 0 || v >= (long long)N_NODES) ok = 0;
        }
        s_is64 = ok;
    }
    __syncthreads();
    const int is64 = s_is64;

    const int warp = threadIdx.x >> 5;
    const int lane = threadIdx.x & 31;
    const int half = lane >> 4;
    const int sub  = lane & 15;
    const long long wbase = ((long long)blockIdx.x * 8 + warp) * 4;
    const long long eA = wbase + half;
    const long long eB = wbase + 2 + half;

    long long sA, dA, sB, dB;
    if (is64) {
        const long long* s64 = (const long long*)srcp;
        const long long* d64 = (const long long*)dstp;
        sA = __ldg(&s64[eA]); dA = __ldg(&d64[eA]);
        sB = __ldg(&s64[eB]); dB = __ldg(&d64[eB]);
    } else {
        const int* s32 = (const int*)srcp;
        const int* d32 = (const int*)dstp;
        sA = __ldg(&s32[eA]); dA = __ldg(&d32[eA]);
        sB = __ldg(&s32[eB]); dB = __ldg(&d32[eB]);
    }

    // Front-batch all 4 gathers (uint2 = 4 halves each)
    uint2 ua0 = *(const uint2*)&g_P[(size_t)sA * PDIM + sub * 4];
    uint2 ua1 = *(const uint2*)&g_P[(size_t)dA * PDIM + OUT_CLASSES + sub * 4];
    uint2 ub0 = *(const uint2*)&g_P[(size_t)sB * PDIM + sub * 4];
    uint2 ub1 = *(const uint2*)&g_P[(size_t)dB * PDIM + OUT_CLASSES + sub * 4];

    float2 a0x = __half22float2(*(__half2*)&ua0.x);
    float2 a0y = __half22float2(*(__half2*)&ua0.y);
    float2 a1x = __half22float2(*(__half2*)&ua1.x);
    float2 a1y = __half22float2(*(__half2*)&ua1.y);
    float2 b0x = __half22float2(*(__half2*)&ub0.x);
    float2 b0y = __half22float2(*(__half2*)&ub0.y);
    float2 b1x = __half22float2(*(__half2*)&ub1.x);
    float2 b1y = __half22float2(*(__half2*)&ub1.y);

    float4 rA = make_float4(a0x.x + a1x.x, a0x.y + a1x.y,
                            a0y.x + a1y.x, a0y.y + a1y.y);
    float4 rB = make_float4(b0x.x + b1x.x, b0x.y + b1x.y,
                            b0y.x + b1y.x, b0y.y + b1y.y);
    __stcs((float4*)&out[(size_t)eA * OUT_CLASSES + sub * 4], rA);
    __stcs((float4*)&out[(size_t)eB * OUT_CLASSES + sub * 4], rB);
}

// ---------------------------------------------------------------------------
// Launch. Inputs: h[50000*128] f32, src[500000], dst[500000],
// W[64*256] f32, b[64] f32. Output: f32[500000*64].
// ---------------------------------------------------------------------------
extern "C" void kernel_launch(void* const* d_in, const int* in_sizes, int n_in,
                              void* d_out, int out_size) {
    const float* h   = (const float*)d_in[0];
    const void*  src = d_in[1];
    const void*  dst = d_in[2];
    const float* W   = (const float*)d_in[3];
    const float* b   = (const float*)d_in[4];
    float* out = (float*)d_out;
    (void)in_sizes; (void)n_in; (void)out_size;

    wsplit_kernel<<<16, 256>>>(W);

    const int gemm_blocks = (N_NODES + GM - 1) / GM;   // 782
    node_gemm_bf16<<<gemm_blocks, 256, GEMM_SMEM>>>(h, b);

    // 32 edges per block (8 warps x 4): 500000/32 = 15625 exactly
    edge_scatter_kernel<<<N_EDGES / 32, 256>>>(src, dst, out);
}

// round 9
// speedup vs baseline: 3.5855x; 1.0873x over previous
#include <cuda_runtime.h>
#include <cuda_fp16.h>
#include <stdint.h>

#define N_NODES     50000
#define N_EDGES     500000
#define D_FEAT      128
#define OUT_CLASSES 64
#define PDIM        128   // [0:64) = Pu (+bias folded), [64:128) = Pv

// Per-node projections in fp16; 12.8 MB, L2-resident.
__device__ __align__(16) __half g_P[N_NODES * PDIM];
// Pre-split W in mma-fragment order: [ng(16)][kc(8)][lane(32)] x uint4
// uint4 = { bhi(pair p0), bhi(pair p0+4), blo(pair p0), blo(pair p0+4) }
__device__ __align__(16) uint4 g_Wfrag[16 * 8 * 32];   // 64 KB, L1/L2-resident

// ---------------------------------------------------------------------------
// 3xBF16 helpers (legacy mma.sync — tcgen05 unavailable at compute_103).
// x = hi + lo (bf16 each, ~17 mantissa bits); P = ah*bh + al*bh + ah*bl.
// ---------------------------------------------------------------------------
__device__ __forceinline__ void split_pair(float x0, float x1,
                                           uint32_t& hi, uint32_t& lo) {
    asm("cvt.rn.bf16x2.f32 %0, %1, %2;" : "=r"(hi) : "f"(x1), "f"(x0));
    float h0 = __uint_as_float(hi << 16);
    float h1 = __uint_as_float(hi & 0xFFFF0000u);
    asm("cvt.rn.bf16x2.f32 %0, %1, %2;" : "=r"(lo) : "f"(x1 - h1), "f"(x0 - h0));
}
__device__ __forceinline__ void mma_bf16(float d[4], const uint32_t a[4], const uint32_t b[2]) {
    asm volatile(
        "mma.sync.aligned.m16n8k16.row.col.f32.bf16.bf16.f32 "
        "{%0,%1,%2,%3}, {%4,%5,%6,%7}, {%8,%9}, {%0,%1,%2,%3};\n"
        : "+f"(d[0]), "+f"(d[1]), "+f"(d[2]), "+f"(d[3])
        : "r"(a[0]), "r"(a[1]), "r"(a[2]), "r"(a[3]), "r"(b[0]), "r"(b[1]));
}

// ---------------------------------------------------------------------------
// Kernel 0: one-shot W split into fragment order. 4096 uint4 total.
// ---------------------------------------------------------------------------
__global__ __launch_bounds__(256)
void wsplit_kernel(const float* __restrict__ W) {
    int t = blockIdx.x * 256 + threadIdx.x;     // 0..4095
    int ng   = t >> 8;
    int kc   = (t >> 5) & 7;
    int lane = t & 31;
    int lr = lane >> 2, lc = lane & 3;
    int n  = ng * 8 + lr;
    const float* wrow = (n < OUT_CLASSES)
        ? &W[(size_t)n * 256]
        : &W[(size_t)(n - OUT_CLASSES) * 256 + 128];
    int p0 = kc * 8 + lc;
    uint32_t h0, l0, h1, l1;
    split_pair(wrow[2 * p0],       wrow[2 * p0 + 1],       h0, l0);
    split_pair(wrow[2 * (p0 + 4)], wrow[2 * (p0 + 4) + 1], h1, l1);
    g_Wfrag[t] = make_uint4(h0, h1, l0, l1);
}

// ---------------------------------------------------------------------------
// Kernel 1: node projection GEMM, 3xBF16, B in g_Wfrag (L1-hit warp-uniform
// LDG.128 fragments), A staged in smem. fp16 epilogue. occ=3 (24 warps/SM)
// to hide the A-staging scoreboard stalls.
// ---------------------------------------------------------------------------
#define GM   64
#define ST   68   // uint32 per row (64 pairs + 4 pad); 68 mod 32 = 4
#define GEMM_SMEM (2 * 64 * ST * 4)   // 34,816 B -> 3 CTAs/SM uses 104KB

__global__ __launch_bounds__(256, 3)
void node_gemm_bf16(const float* __restrict__ h,
                    const float* __restrict__ b) {
    extern __shared__ uint32_t sh[];
    uint32_t* Ahi = sh;
    uint32_t* Alo = sh + 64 * ST;

    const int tid = threadIdx.x;
    const int n0  = blockIdx.x * GM;

    // Stage A (h tile, 64 x 128 f32 -> bf16x2 hi/lo)
    #pragma unroll
    for (int it = 0; it < 8; ++it) {
        int idx = tid + it * 256;          // 0..2047
        int r  = idx >> 5;                 // 0..63
        int c4 = idx & 31;                 // float4 index; k = c4*4
        int node = n0 + r;
        float4 v = make_float4(0.f, 0.f, 0.f, 0.f);
        if (node < N_NODES)
            v = __ldg((const float4*)&h[(size_t)node * D_FEAT + c4 * 4]);
        uint32_t h0, l0, h1, l1;
        split_pair(v.x, v.y, h0, l0);
        split_pair(v.z, v.w, h1, l1);
        int p = r * ST + c4 * 2;
        *(uint2*)&Ahi[p] = make_uint2(h0, h1);
        *(uint2*)&Alo[p] = make_uint2(l0, l1);
    }
    __syncthreads();

    const int wid    = tid >> 5;
    const int lane   = tid & 31;
    const int warp_m = wid & 1;        // 2 warps over 64 m
    const int warp_n = wid >> 1;       // 4 warps over 128 n
    const int m_base = warp_m * 32;
    const int lr = lane >> 2;          // 0..7
    const int lc = lane & 3;           // 0..3

    const uint4* wf = &g_Wfrag[(warp_n * 4) * 8 * 32 + lane];

    float acc[2][4][4];
    #pragma unroll
    for (int a = 0; a < 2; ++a)
        #pragma unroll
        for (int bn = 0; bn < 4; ++bn)
            #pragma unroll
            for (int c = 0; c < 4; ++c) acc[a][bn][c] = 0.0f;

    #pragma unroll 2
    for (int kc = 0; kc < 8; ++kc) {
        const int p0 = kc * 8;

        uint4 bf[4];
        #pragma unroll
        for (int bn = 0; bn < 4; ++bn)
            bf[bn] = __ldg(&wf[(bn * 8 + kc) * 32]);

        uint32_t ah[2][4], al[2][4];
        #pragma unroll
        for (int am = 0; am < 2; ++am) {
            int base = (m_base + am * 16 + lr) * ST + p0 + lc;
            ah[am][0] = Ahi[base];
            ah[am][1] = Ahi[base + 8 * ST];
            ah[am][2] = Ahi[base + 4];
            ah[am][3] = Ahi[base + 8 * ST + 4];
            al[am][0] = Alo[base];
            al[am][1] = Alo[base + 8 * ST];
            al[am][2] = Alo[base + 4];
            al[am][3] = Alo[base + 8 * ST + 4];
        }
        #pragma unroll
        for (int am = 0; am < 2; ++am)
            #pragma unroll
            for (int bn = 0; bn < 4; ++bn) {
                uint32_t bh[2] = { bf[bn].x, bf[bn].y };
                uint32_t bl[2] = { bf[bn].z, bf[bn].w };
                mma_bf16(acc[am][bn], ah[am], bh);
                mma_bf16(acc[am][bn], al[am], bh);
                mma_bf16(acc[am][bn], ah[am], bl);
            }
    }

    // Epilogue: fp16 P, bias folded into Pu columns.
    #pragma unroll
    for (int am = 0; am < 2; ++am) {
        int row = m_base + am * 16 + lr;
        #pragma unroll
        for (int bn = 0; bn < 4; ++bn) {
            int j = warp_n * 32 + bn * 8 + 2 * lc;
            float bx = 0.f, by = 0.f;
            if (warp_n < 2) {
                float2 bv = __ldg((const float2*)&b[j]);
                bx = bv.x; by = bv.y;
            }
            int node = n0 + row;
            if (node < N_NODES) {
                __half2 v0 = __floats2half2_rn(acc[am][bn][0] + bx,
                                               acc[am][bn][1] + by);
                *(__half2*)&g_P[(size_t)node * PDIM + j] = v0;
            }
            int node2 = n0 + row + 8;
            if (node2 < N_NODES) {
                __half2 v1 = __floats2half2_rn(acc[am][bn][2] + bx,
                                               acc[am][bn][3] + by);
                *(__half2*)&g_P[(size_t)node2 * PDIM + j] = v1;
            }
        }
    }
}

// ---------------------------------------------------------------------------
// Kernel 2: edge scatter on fp16 P. 8 edges/warp (4 per half-warp), all
// index loads and all 8 row-gathers front-batched (MLP 8+). Streaming
// float4 output stores. Loads use clamped edge ids; stores are guarded.
// ---------------------------------------------------------------------------
__global__ __launch_bounds__(256)
void edge_scatter_kernel(const void* __restrict__ srcp,
                         const void* __restrict__ dstp,
                         float* __restrict__ out) {
    __shared__ int s_is64;
    if (threadIdx.x == 0) {
        const long long* s64 = (const long long*)srcp;
        int ok = 1;
        #pragma unroll
        for (int i = 0; i < 8; ++i) {
            long long v = s64[i];
            if (v < 0 || v >= (long long)N_NODES) ok = 0;
        }
        s_is64 = ok;
    }
    __syncthreads();
    const int is64 = s_is64;

    const int warp = threadIdx.x >> 5;
    const int lane = threadIdx.x & 31;
    const int half = lane >> 4;
    const int sub  = lane & 15;
    // 8 warps x 8 edges per block; half-warp handles 4 consecutive edges
    const long long ebase = ((long long)blockIdx.x * 8 + warp) * 8 + half * 4;

    long long e[4], s[4], d[4];
    #pragma unroll
    for (int i = 0; i < 4; ++i) {
        e[i] = ebase + i;
        long long ec = e[i] < N_EDGES ? e[i] : (long long)(N_EDGES - 1);
        if (is64) {
            s[i] = __ldg(&((const long long*)srcp)[ec]);
            d[i] = __ldg(&((const long long*)dstp)[ec]);
        } else {
            s[i] = __ldg(&((const int*)srcp)[ec]);
            d[i] = __ldg(&((const int*)dstp)[ec]);
        }
    }

    // Front-batch all 8 gathers (uint2 = 4 halves each; 16 lanes x 8B = 128B/row)
    uint2 gu[4], gv[4];
    #pragma unroll
    for (int i = 0; i < 4; ++i) {
        gu[i] = *(const uint2*)&g_P[(size_t)s[i] * PDIM + sub * 4];
        gv[i] = *(const uint2*)&g_P[(size_t)d[i] * PDIM + OUT_CLASSES + sub * 4];
    }

    #pragma unroll
    for (int i = 0; i < 4; ++i) {
        float2 ux = __half22float2(*(__half2*)&gu[i].x);
        float2 uy = __half22float2(*(__half2*)&gu[i].y);
        float2 vx = __half22float2(*(__half2*)&gv[i].x);
        float2 vy = __half22float2(*(__half2*)&gv[i].y);
        float4 r = make_float4(ux.x + vx.x, ux.y + vx.y,
                               uy.x + vy.x, uy.y + vy.y);
        if (e[i] < N_EDGES)
            __stcs((float4*)&out[(size_t)e[i] * OUT_CLASSES + sub * 4], r);
    }
}

// ---------------------------------------------------------------------------
// Launch. Inputs: h[50000*128] f32, src[500000], dst[500000],
// W[64*256] f32, b[64] f32. Output: f32[500000*64].
// ---------------------------------------------------------------------------
extern "C" void kernel_launch(void* const* d_in, const int* in_sizes, int n_in,
                              void* d_out, int out_size) {
    const float* h   = (const float*)d_in[0];
    const void*  src = d_in[1];
    const void*  dst = d_in[2];
    const float* W   = (const float*)d_in[3];
    const float* b   = (const float*)d_in[4];
    float* out = (float*)d_out;
    (void)in_sizes; (void)n_in; (void)out_size;

    wsplit_kernel<<<16, 256>>>(W);

    const int gemm_blocks = (N_NODES + GM - 1) / GM;   // 782
    node_gemm_bf16<<<gemm_blocks, 256, GEMM_SMEM>>>(h, b);

    // 64 edges per block (8 warps x 8): ceil(500000/64) = 7813
    edge_scatter_kernel<<<(N_EDGES + 63) / 64, 256>>>(src, dst, out);
}

// round 10
// speedup vs baseline: 3.7836x; 1.0553x over previous
#include <cuda_runtime.h>
#include <cuda_fp16.h>
#include <stdint.h>

#define N_NODES     50000
#define N_EDGES     500000
#define D_FEAT      128
#define OUT_CLASSES 64
#define PDIM        128   // [0:64) = Pu (+bias folded), [64:128) = Pv

// Per-node projections in fp16; 12.8 MB, L2-resident.
__device__ __align__(16) __half g_P[N_NODES * PDIM];
// Pre-converted W (fp16) in mma-fragment order: [ng(16)][kc(8)][lane(32)] x uint2
// uint2 = { bh(pair p0), bh(pair p0+4) }, pair p = f16x2 of (Wn[n][2p], Wn[n][2p+1]),
// n = ng*8 + (lane>>2), p0 = kc*8 + (lane&3),
// Wn[j][k] = (j<64) ? W[j][k] : W[j-64][128+k].   32 KB, L1-resident.
__device__ __align__(16) uint2 g_Wfrag[16 * 8 * 32];

// ---------------------------------------------------------------------------
// 2-pass fp16 scheme (legacy mma.sync — tcgen05 unavailable at compute_103):
// A split x = ah + al (fp16 each, exact to ~2^-22); B single fp16.
// P = (ah + al) * bh  ->  mma(ah,bh) + mma(al,bh).  Only B's fp16 rounding
// (~2.8e-4 rms) survives; total with fp16-P storage ~3.5e-4 << 1e-3.
// ---------------------------------------------------------------------------
__device__ __forceinline__ void split_pair_f16(float x0, float x1,
                                               uint32_t& hi, uint32_t& lo) {
    __half2 h = __floats2half2_rn(x0, x1);
    hi = *(uint32_t*)&h;
    float2 back = __half22float2(h);
    __half2 l = __floats2half2_rn(x0 - back.x, x1 - back.y);
    lo = *(uint32_t*)&l;
}
__device__ __forceinline__ void mma_f16(float d[4], const uint32_t a[4], const uint32_t b[2]) {
    asm volatile(
        "mma.sync.aligned.m16n8k16.row.col.f32.f16.f16.f32 "
        "{%0,%1,%2,%3}, {%4,%5,%6,%7}, {%8,%9}, {%0,%1,%2,%3};\n"
        : "+f"(d[0]), "+f"(d[1]), "+f"(d[2]), "+f"(d[3])
        : "r"(a[0]), "r"(a[1]), "r"(a[2]), "r"(a[3]), "r"(b[0]), "r"(b[1]));
}

// ---------------------------------------------------------------------------
// Kernel 0: one-shot W -> fp16 fragment order. 4096 uint2 total.
// ---------------------------------------------------------------------------
__global__ __launch_bounds__(256)
void wsplit_kernel(const float* __restrict__ W) {
    int t = blockIdx.x * 256 + threadIdx.x;     // 0..4095
    int ng   = t >> 8;
    int kc   = (t >> 5) & 7;
    int lane = t & 31;
    int lr = lane >> 2, lc = lane & 3;
    int n  = ng * 8 + lr;
    const float* wrow = (n < OUT_CLASSES)
        ? &W[(size_t)n * 256]
        : &W[(size_t)(n - OUT_CLASSES) * 256 + 128];
    int p0 = kc * 8 + lc;
    __half2 h0 = __floats2half2_rn(wrow[2 * p0],       wrow[2 * p0 + 1]);
    __half2 h1 = __floats2half2_rn(wrow[2 * (p0 + 4)], wrow[2 * (p0 + 4) + 1]);
    g_Wfrag[t] = make_uint2(*(uint32_t*)&h0, *(uint32_t*)&h1);
}

// ---------------------------------------------------------------------------
// Kernel 1: node projection GEMM, 2-pass fp16. B fragments via warp-uniform
// LDG.64 from g_Wfrag (L1-hit); A hi/lo staged in smem; fp16 epilogue.
// Tile 64 nodes x 128 outputs x K=128; occ=3 (24 warps/SM).
// ---------------------------------------------------------------------------
#define GM   64
#define ST   68   // uint32 per row (64 pairs + 4 pad); 68 mod 32 = 4
#define GEMM_SMEM (2 * 64 * ST * 4)   // 34,816 B

__global__ __launch_bounds__(256, 3)
void node_gemm_f16(const float* __restrict__ h,
                   const float* __restrict__ b) {
    extern __shared__ uint32_t sh[];
    uint32_t* Ahi = sh;
    uint32_t* Alo = sh + 64 * ST;

    const int tid = threadIdx.x;
    const int n0  = blockIdx.x * GM;

    // Stage A (h tile, 64 x 128 f32 -> f16x2 hi/lo)
    #pragma unroll
    for (int it = 0; it < 8; ++it) {
        int idx = tid + it * 256;          // 0..2047
        int r  = idx >> 5;                 // 0..63
        int c4 = idx & 31;                 // float4 index; k = c4*4
        int node = n0 + r;
        float4 v = make_float4(0.f, 0.f, 0.f, 0.f);
        if (node < N_NODES)
            v = __ldg((const float4*)&h[(size_t)node * D_FEAT + c4 * 4]);
        uint32_t h0, l0, h1, l1;
        split_pair_f16(v.x, v.y, h0, l0);
        split_pair_f16(v.z, v.w, h1, l1);
        int p = r * ST + c4 * 2;
        *(uint2*)&Ahi[p] = make_uint2(h0, h1);
        *(uint2*)&Alo[p] = make_uint2(l0, l1);
    }
    __syncthreads();

    const int wid    = tid >> 5;
    const int lane   = tid & 31;
    const int warp_m = wid & 1;        // 2 warps over 64 m
    const int warp_n = wid >> 1;       // 4 warps over 128 n
    const int m_base = warp_m * 32;
    const int lr = lane >> 2;          // 0..7
    const int lc = lane & 3;           // 0..3

    const uint2* wf = &g_Wfrag[(warp_n * 4) * 8 * 32 + lane];

    float acc[2][4][4];
    #pragma unroll
    for (int a = 0; a < 2; ++a)
        #pragma unroll
        for (int bn = 0; bn < 4; ++bn)
            #pragma unroll
            for (int c = 0; c < 4; ++c) acc[a][bn][c] = 0.0f;

    #pragma unroll 2
    for (int kc = 0; kc < 8; ++kc) {
        const int p0 = kc * 8;

        // B fragments: 4 x LDG.64, warp-uniform addresses, L1-resident.
        uint2 bf[4];
        #pragma unroll
        for (int bn = 0; bn < 4; ++bn)
            bf[bn] = __ldg(&wf[(bn * 8 + kc) * 32]);

        uint32_t ah[2][4], al[2][4];
        #pragma unroll
        for (int am = 0; am < 2; ++am) {
            int base = (m_base + am * 16 + lr) * ST + p0 + lc;
            ah[am][0] = Ahi[base];
            ah[am][1] = Ahi[base + 8 * ST];
            ah[am][2] = Ahi[base + 4];
            ah[am][3] = Ahi[base + 8 * ST + 4];
            al[am][0] = Alo[base];
            al[am][1] = Alo[base + 8 * ST];
            al[am][2] = Alo[base + 4];
            al[am][3] = Alo[base + 8 * ST + 4];
        }
        #pragma unroll
        for (int am = 0; am < 2; ++am)
            #pragma unroll
            for (int bn = 0; bn < 4; ++bn) {
                uint32_t bh[2] = { bf[bn].x, bf[bn].y };
                mma_f16(acc[am][bn], ah[am], bh);
                mma_f16(acc[am][bn], al[am], bh);
            }
    }

    // Epilogue: fp16 P, bias folded into Pu columns.
    #pragma unroll
    for (int am = 0; am < 2; ++am) {
        int row = m_base + am * 16 + lr;
        #pragma unroll
        for (int bn = 0; bn < 4; ++bn) {
            int j = warp_n * 32 + bn * 8 + 2 * lc;
            float bx = 0.f, by = 0.f;
            if (warp_n < 2) {
                float2 bv = __ldg((const float2*)&b[j]);
                bx = bv.x; by = bv.y;
            }
            int node = n0 + row;
            if (node < N_NODES) {
                __half2 v0 = __floats2half2_rn(acc[am][bn][0] + bx,
                                               acc[am][bn][1] + by);
                *(__half2*)&g_P[(size_t)node * PDIM + j] = v0;
            }
            int node2 = n0 + row + 8;
            if (node2 < N_NODES) {
                __half2 v1 = __floats2half2_rn(acc[am][bn][2] + bx,
                                               acc[am][bn][3] + by);
                *(__half2*)&g_P[(size_t)node2 * PDIM + j] = v1;
            }
        }
    }
}

// ---------------------------------------------------------------------------
// Kernel 2: edge scatter on fp16 P. 8 edges/warp (4 per half-warp), all
// index loads and all 8 row-gathers front-batched (MLP 8+). Streaming
// float4 output stores; guarded tail.
// ---------------------------------------------------------------------------
__global__ __launch_bounds__(256)
void edge_scatter_kernel(const void* __restrict__ srcp,
                         const void* __restrict__ dstp,
                         float* __restrict__ out) {
    __shared__ int s_is64;
    if (threadIdx.x == 0) {
        const long long* s64 = (const long long*)srcp;
        int ok = 1;
        #pragma unroll
        for (int i = 0; i < 8; ++i) {
            long long v = s64[i];
            if (v < 0 || v >= (long long)N_NODES) ok = 0;
        }
        s_is64 = ok;
    }
    __syncthreads();
    const int is64 = s_is64;

    const int warp = threadIdx.x >> 5;
    const int lane = threadIdx.x & 31;
    const int half = lane >> 4;
    const int sub  = lane & 15;
    const long long ebase = ((long long)blockIdx.x * 8 + warp) * 8 + half * 4;

    long long e[4], s[4], d[4];
    #pragma unroll
    for (int i = 0; i < 4; ++i) {
        e[i] = ebase + i;
        long long ec = e[i] < N_EDGES ? e[i] : (long long)(N_EDGES - 1);
        if (is64) {
            s[i] = __ldg(&((const long long*)srcp)[ec]);
            d[i] = __ldg(&((const long long*)dstp)[ec]);
        } else {
            s[i] = __ldg(&((const int*)srcp)[ec]);
            d[i] = __ldg(&((const int*)dstp)[ec]);
        }
    }

    uint2 gu[4], gv[4];
    #pragma unroll
    for (int i = 0; i < 4; ++i) {
        gu[i] = *(const uint2*)&g_P[(size_t)s[i] * PDIM + sub * 4];
        gv[i] = *(const uint2*)&g_P[(size_t)d[i] * PDIM + OUT_CLASSES + sub * 4];
    }

    #pragma unroll
    for (int i = 0; i < 4; ++i) {
        float2 ux = __half22float2(*(__half2*)&gu[i].x);
        float2 uy = __half22float2(*(__half2*)&gu[i].y);
        float2 vx = __half22float2(*(__half2*)&gv[i].x);
        float2 vy = __half22float2(*(__half2*)&gv[i].y);
        float4 r = make_float4(ux.x + vx.x, ux.y + vx.y,
                               uy.x + vy.x, uy.y + vy.y);
        if (e[i] < N_EDGES)
            __stcs((float4*)&out[(size_t)e[i] * OUT_CLASSES + sub * 4], r);
    }
}

// ---------------------------------------------------------------------------
// Launch. Inputs: h[50000*128] f32, src[500000], dst[500000],
// W[64*256] f32, b[64] f32. Output: f32[500000*64].
// ---------------------------------------------------------------------------
extern "C" void kernel_launch(void* const* d_in, const int* in_sizes, int n_in,
                              void* d_out, int out_size) {
    const float* h   = (const float*)d_in[0];
    const void*  src = d_in[1];
    const void*  dst = d_in[2];
    const float* W   = (const float*)d_in[3];
    const float* b   = (const float*)d_in[4];
    float* out = (float*)d_out;
    (void)in_sizes; (void)n_in; (void)out_size;

    wsplit_kernel<<<16, 256>>>(W);

    const int gemm_blocks = (N_NODES + GM - 1) / GM;   // 782
    node_gemm_f16<<<gemm_blocks, 256, GEMM_SMEM>>>(h, b);

    // 64 edges per block (8 warps x 8): ceil(500000/64) = 7813
    edge_scatter_kernel<<<(N_EDGES + 63) / 64, 256>>>(src, dst, out);
}

// round 11
// speedup vs baseline: 3.8486x; 1.0172x over previous
#include <cuda_runtime.h>
#include <cuda_fp16.h>
#include <stdint.h>

#define N_NODES     50000
#define N_EDGES     500000
#define D_FEAT      128
#define OUT_CLASSES 64
#define PDIM        128   // [0:64) = Pu (+bias folded), [64:128) = Pv

// Per-node projections in fp16; 12.8 MB, L2-resident.
__device__ __align__(16) __half g_P[N_NODES * PDIM];
// Pre-converted W (fp16) in mma-fragment order: [ng(16)][kc(8)][lane(32)] x uint2
// uint2 = { b(pair p0), b(pair p0+4) }, pair p = f16x2 of (Wn[n][2p], Wn[n][2p+1]),
// n = ng*8 + (lane>>2), p0 = kc*8 + (lane&3),
// Wn[j][k] = (j<64) ? W[j][k] : W[j-64][128+k].   32 KB, L1-resident.
__device__ __align__(16) uint2 g_Wfrag[16 * 8 * 32];

// ---------------------------------------------------------------------------
// Single-pass fp16 mma (legacy mma.sync — tcgen05 unavailable at compute_103).
// Error sources (measured, quadrature): fp16-P 2.07e-4, fp16-B 2.07e-4,
// fp16-A 2.07e-4 -> total ~3.6e-4 << 1e-3.
// ---------------------------------------------------------------------------
__device__ __forceinline__ void mma_f16(float d[4], const uint32_t a[4], const uint32_t b[2]) {
    asm volatile(
        "mma.sync.aligned.m16n8k16.row.col.f32.f16.f16.f32 "
        "{%0,%1,%2,%3}, {%4,%5,%6,%7}, {%8,%9}, {%0,%1,%2,%3};\n"
        : "+f"(d[0]), "+f"(d[1]), "+f"(d[2]), "+f"(d[3])
        : "r"(a[0]), "r"(a[1]), "r"(a[2]), "r"(a[3]), "r"(b[0]), "r"(b[1]));
}

// ---------------------------------------------------------------------------
// Kernel 0: one-shot W -> fp16 fragment order. 4096 uint2 total.
// ---------------------------------------------------------------------------
__global__ __launch_bounds__(256)
void wsplit_kernel(const float* __restrict__ W) {
    int t = blockIdx.x * 256 + threadIdx.x;     // 0..4095
    int ng   = t >> 8;
    int kc   = (t >> 5) & 7;
    int lane = t & 31;
    int lr = lane >> 2, lc = lane & 3;
    int n  = ng * 8 + lr;
    const float* wrow = (n < OUT_CLASSES)
        ? &W[(size_t)n * 256]
        : &W[(size_t)(n - OUT_CLASSES) * 256 + 128];
    int p0 = kc * 8 + lc;
    __half2 h0 = __floats2half2_rn(wrow[2 * p0],       wrow[2 * p0 + 1]);
    __half2 h1 = __floats2half2_rn(wrow[2 * (p0 + 4)], wrow[2 * (p0 + 4) + 1]);
    g_Wfrag[t] = make_uint2(*(uint32_t*)&h0, *(uint32_t*)&h1);
}

// ---------------------------------------------------------------------------
// Kernel 1: node projection GEMM, single-pass fp16. B fragments via
// warp-uniform LDG.64 from g_Wfrag (L1-hit); A (fp16) staged in smem;
// fp16 epilogue with bias folded into Pu. Tile 64m x 128n x 128k.
// smem 17.4KB; occ=4 (32 warps/SM) hides the A-staging scoreboard stalls.
// ---------------------------------------------------------------------------
#define GM   64
#define ST   68   // uint32 per row (64 f16x2 pairs + 4 pad); 68 mod 32 = 4
#define GEMM_SMEM (64 * ST * 4)   // 17,408 B

__global__ __launch_bounds__(256, 4)
void node_gemm_f16(const float* __restrict__ h,
                   const float* __restrict__ b) {
    extern __shared__ uint32_t sh[];
    uint32_t* Ah = sh;   // [64][ST] f16x2 pairs, k-major

    const int tid = threadIdx.x;
    const int n0  = blockIdx.x * GM;

    // Stage A (h tile, 64 x 128 f32 -> f16x2)
    #pragma unroll
    for (int it = 0; it < 8; ++it) {
        int idx = tid + it * 256;          // 0..2047
        int r  = idx >> 5;                 // 0..63
        int c4 = idx & 31;                 // float4 index; k = c4*4
        int node = n0 + r;
        float4 v = make_float4(0.f, 0.f, 0.f, 0.f);
        if (node < N_NODES)
            v = __ldg((const float4*)&h[(size_t)node * D_FEAT + c4 * 4]);
        __half2 h0 = __floats2half2_rn(v.x, v.y);
        __half2 h1 = __floats2half2_rn(v.z, v.w);
        *(uint2*)&Ah[r * ST + c4 * 2] = make_uint2(*(uint32_t*)&h0, *(uint32_t*)&h1);
    }
    __syncthreads();

    const int wid    = tid >> 5;
    const int lane   = tid & 31;
    const int warp_m = wid & 1;        // 2 warps over 64 m
    const int warp_n = wid >> 1;       // 4 warps over 128 n
    const int m_base = warp_m * 32;
    const int lr = lane >> 2;          // 0..7
    const int lc = lane & 3;           // 0..3

    const uint2* wf = &g_Wfrag[(warp_n * 4) * 8 * 32 + lane];

    float acc[2][4][4];
    #pragma unroll
    for (int a = 0; a < 2; ++a)
        #pragma unroll
        for (int bn = 0; bn < 4; ++bn)
            #pragma unroll
            for (int c = 0; c < 4; ++c) acc[a][bn][c] = 0.0f;

    #pragma unroll 2
    for (int kc = 0; kc < 8; ++kc) {
        const int p0 = kc * 8;

        // B fragments: 4 x LDG.64, warp-uniform addresses, L1-resident.
        uint2 bf[4];
        #pragma unroll
        for (int bn = 0; bn < 4; ++bn)
            bf[bn] = __ldg(&wf[(bn * 8 + kc) * 32]);

        uint32_t ah[2][4];
        #pragma unroll
        for (int am = 0; am < 2; ++am) {
            int base = (m_base + am * 16 + lr) * ST + p0 + lc;
            ah[am][0] = Ah[base];
            ah[am][1] = Ah[base + 8 * ST];
            ah[am][2] = Ah[base + 4];
            ah[am][3] = Ah[base + 8 * ST + 4];
        }
        #pragma unroll
        for (int am = 0; am < 2; ++am)
            #pragma unroll
            for (int bn = 0; bn < 4; ++bn) {
                uint32_t bb[2] = { bf[bn].x, bf[bn].y };
                mma_f16(acc[am][bn], ah[am], bb);
            }
    }

    // Epilogue: fp16 P, bias folded into Pu columns.
    #pragma unroll
    for (int am = 0; am < 2; ++am) {
        int row = m_base + am * 16 + lr;
        #pragma unroll
        for (int bn = 0; bn < 4; ++bn) {
            int j = warp_n * 32 + bn * 8 + 2 * lc;
            float bx = 0.f, by = 0.f;
            if (warp_n < 2) {
                float2 bv = __ldg((const float2*)&b[j]);
                bx = bv.x; by = bv.y;
            }
            int node = n0 + row;
            if (node < N_NODES) {
                __half2 v0 = __floats2half2_rn(acc[am][bn][0] + bx,
                                               acc[am][bn][1] + by);
                *(__half2*)&g_P[(size_t)node * PDIM + j] = v0;
            }
            int node2 = n0 + row + 8;
            if (node2 < N_NODES) {
                __half2 v1 = __floats2half2_rn(acc[am][bn][2] + bx,
                                               acc[am][bn][3] + by);
                *(__half2*)&g_P[(size_t)node2 * PDIM + j] = v1;
            }
        }
    }
}

// ---------------------------------------------------------------------------
// Kernel 2: edge scatter on fp16 P. 8 edges/warp (4 per half-warp), all
// index loads and all 8 row-gathers front-batched (MLP 8+). Streaming
// float4 output stores; guarded tail.
// ---------------------------------------------------------------------------
__global__ __launch_bounds__(256)
void edge_scatter_kernel(const void* __restrict__ srcp,
                         const void* __restrict__ dstp,
                         float* __restrict__ out) {
    __shared__ int s_is64;
    if (threadIdx.x == 0) {
        const long long* s64 = (const long long*)srcp;
        int ok = 1;
        #pragma unroll
        for (int i = 0; i < 8; ++i) {
            long long v = s64[i];
            if (v < 0 || v >= (long long)N_NODES) ok = 0;
        }
        s_is64 = ok;
    }
    __syncthreads();
    const int is64 = s_is64;

    const int warp = threadIdx.x >> 5;
    const int lane = threadIdx.x & 31;
    const int half = lane >> 4;
    const int sub  = lane & 15;
    const long long ebase = ((long long)blockIdx.x * 8 + warp) * 8 + half * 4;

    long long e[4], s[4], d[4];
    #pragma unroll
    for (int i = 0; i < 4; ++i) {
        e[i] = ebase + i;
        long long ec = e[i] < N_EDGES ? e[i] : (long long)(N_EDGES - 1);
        if (is64) {
            s[i] = __ldg(&((const long long*)srcp)[ec]);
            d[i] = __ldg(&((const long long*)dstp)[ec]);
        } else {
            s[i] = __ldg(&((const int*)srcp)[ec]);
            d[i] = __ldg(&((const int*)dstp)[ec]);
        }
    }

    uint2 gu[4], gv[4];
    #pragma unroll
    for (int i = 0; i < 4; ++i) {
        gu[i] = *(const uint2*)&g_P[(size_t)s[i] * PDIM + sub * 4];
        gv[i] = *(const uint2*)&g_P[(size_t)d[i] * PDIM + OUT_CLASSES + sub * 4];
    }

    #pragma unroll
    for (int i = 0; i < 4; ++i) {
        float2 ux = __half22float2(*(__half2*)&gu[i].x);
        float2 uy = __half22float2(*(__half2*)&gu[i].y);
        float2 vx = __half22float2(*(__half2*)&gv[i].x);
        float2 vy = __half22float2(*(__half2*)&gv[i].y);
        float4 r = make_float4(ux.x + vx.x, ux.y + vx.y,
                               uy.x + vy.x, uy.y + vy.y);
        if (e[i] < N_EDGES)
            __stcs((float4*)&out[(size_t)e[i] * OUT_CLASSES + sub * 4], r);
    }
}

// ---------------------------------------------------------------------------
// Launch. Inputs: h[50000*128] f32, src[500000], dst[500000],
// W[64*256] f32, b[64] f32. Output: f32[500000*64].
// ---------------------------------------------------------------------------
extern "C" void kernel_launch(void* const* d_in, const int* in_sizes, int n_in,
                              void* d_out, int out_size) {
    const float* h   = (const float*)d_in[0];
    const void*  src = d_in[1];
    const void*  dst = d_in[2];
    const float* W   = (const float*)d_in[3];
    const float* b   = (const float*)d_in[4];
    float* out = (float*)d_out;
    (void)in_sizes; (void)n_in; (void)out_size;

    wsplit_kernel<<<16, 256>>>(W);

    const int gemm_blocks = (N_NODES + GM - 1) / GM;   // 782
    node_gemm_f16<<<gemm_blocks, 256, GEMM_SMEM>>>(h, b);

    // 64 edges per block (8 warps x 8): ceil(500000/64) = 7813
    edge_scatter_kernel<<<(N_EDGES + 63) / 64, 256>>>(src, dst, out);
}